// round 8
// baseline (speedup 1.0000x reference)
#include <cuda_runtime.h>
#include <math.h>
#include <stdint.h>

#define NTOK 64
#define CDIM 256
#define NHEADS 8
#define HD   32
#define QS   260          // row stride (floats) for q/k/v smem buffers
#define NWIN 64
#define NBATCH 2048
#define THREADS 256

#define SMEM_FLOATS (3 * NTOK * QS)
#define SMEM_BYTES  (SMEM_FLOATS * 4)     // 199680 B

__device__ float d_tbl2[225 * NHEADS];
__device__ float d_Tcomb[NWIN * NHEADS * NTOK * NTOK];   // 16*sigmoid(bias)+mask, 8MB
__device__ uint32_t d_wtf[4 * 32768];                    // q,k,v,p weights as tf32 bits

// ---------------- prologue 0: weights -> tf32 bits ----------------
__device__ __forceinline__ uint32_t f2tf(float f) {
    uint32_t u; asm("cvt.rna.tf32.f32 %0, %1;" : "=r"(u) : "f"(f)); return u;
}

__global__ void wconv_kernel(const float* __restrict__ qw, const float* __restrict__ kw,
                             const float* __restrict__ vw, const float* __restrict__ pw) {
    int idx = blockIdx.x * blockDim.x + threadIdx.x;
    if (idx >= 4 * 32768) return;
    int sel = idx >> 15, off = idx & 32767;
    float v = (sel == 0) ? qw[off] : (sel == 1) ? kw[off] : (sel == 2) ? vw[off] : pw[off];
    d_wtf[idx] = f2tf(v);
}

// ---------------- prologue 1: rpb_table -> MLP -> (225, 8) ----------------
__global__ void cpb_mlp_kernel(const float* __restrict__ rpb,
                               const float* __restrict__ w1,
                               const float* __restrict__ b1,
                               const float* __restrict__ w2) {
    __shared__ float acc[NHEADS];
    int p = blockIdx.x;          // 0..224
    int j = threadIdx.x;         // 0..127
    if (j < NHEADS) acc[j] = 0.f;
    __syncthreads();
    float t0 = rpb[p * 2 + 0];
    float t1 = rpb[p * 2 + 1];
    float hid = fmaxf(t0 * w1[j] + t1 * w1[128 + j] + b1[j], 0.f);
#pragma unroll
    for (int h = 0; h < NHEADS; ++h) {
        float pv = hid * w2[j * 8 + h];
#pragma unroll
        for (int o = 16; o; o >>= 1) pv += __shfl_xor_sync(0xffffffffu, pv, o);
        if ((j & 31) == 0) atomicAdd(&acc[h], pv);
    }
    __syncthreads();
    if (j < NHEADS) d_tbl2[p * 8 + j] = acc[j];
}

// ---------------- prologue 2: combined bias+mask table ----------------
__global__ void bias_combine_kernel(const int* __restrict__ rpi,
                                    const float* __restrict__ mask) {
    int idx = blockIdx.x * blockDim.x + threadIdx.x;
    if (idx >= NWIN * NHEADS * NTOK * NTOK) return;
    int ij = idx & 4095;
    int h  = (idx >> 12) & 7;
    int w  = idx >> 15;
    float bv = d_tbl2[rpi[ij] * 8 + h];
    d_Tcomb[idx] = 16.f / (1.f + expf(-bv)) + mask[w * 4096 + ij];
}

// ---------------- mma helper ----------------
__device__ __forceinline__ void mma_tf32(float& d0, float& d1, float& d2, float& d3,
                                         uint32_t a0, uint32_t a1, uint32_t a2, uint32_t a3,
                                         uint32_t b0, uint32_t b1) {
    asm volatile(
        "mma.sync.aligned.m16n8k8.row.col.f32.tf32.tf32.f32 "
        "{%0,%1,%2,%3},{%4,%5,%6,%7},{%8,%9},{%0,%1,%2,%3};"
        : "+f"(d0), "+f"(d1), "+f"(d2), "+f"(d3)
        : "r"(a0), "r"(a1), "r"(a2), "r"(a3), "r"(b0), "r"(b1));
}

// weight source in d_wtf: w 0..3 = q,k,v,p
#define WSRC(w, s, hf) (d_wtf + (w) * 32768 + (s) * 16384 + (hf) * 8192)

// stage buffer for stage index T (compile-time literal after unrolling):
// even -> vsm strip, odd -> kss strip; col region 128 for stages 6..11
#define BUF_PTR(T) ((const uint32_t*)((((T) & 1) ? (void*)kss : (void*)vsm)) + \
                    ((((T) >= 6) && ((T) < 12)) ? 128 : 0))
#define BUF_ADR(T) (((((T) & 1) ? kss_u : vsm_u)) + ((((T) >= 6) && ((T) < 12)) ? 512u : 0u))

// issue the 8 cp.async for one [64][128] weight stage + commit.
// SWIZZLE: physical col = (col + 4*(row&7)) & 127; row&7 == ldrow for all k_,
// so the shift is a per-thread constant (sdcol).
#define ISSUE(SRC, DSTU) do {                                                \
    const uint32_t* _s0 = (SRC) + ldrow * 128 + ldcol;                       \
    uint32_t _d0 = (DSTU) + (uint32_t)((ldrow * QS + sdcol) * 4);            \
    _Pragma("unroll")                                                        \
    for (int k_ = 0; k_ < 8; ++k_)                                           \
        asm volatile("cp.async.cg.shared.global [%0], [%1], 16;\n"           \
            :: "r"(_d0 + (uint32_t)(k_ * 8 * QS * 4)),                       \
               "l"(_s0 + k_ * 8 * 128) : "memory");                          \
    asm volatile("cp.async.commit_group;\n" ::: "memory");                   \
} while (0)

// 32x32 warp-tile mma over one swizzle-staged [64 K][128 N] weight tile.
// cb0 = n0 + qr + 4*ql, cb1 = cb0 + 16 (per-lane consts, defined in kernel).
#define MMA_LOOP32(BUFP, ACC) do {                                           \
    const uint32_t* _bu = (BUFP);                                            \
    _Pragma("unroll")                                                        \
    for (int kt = 0; kt < 8; ++kt) {                                         \
        const uint32_t* r0p = _bu + (kt * 8 + ql) * QS;                      \
        const uint32_t* r1p = _bu + (kt * 8 + ql + 4) * QS;                  \
        _Pragma("unroll")                                                    \
        for (int nt = 0; nt < 4; ++nt) {                                     \
            uint32_t b0_ = r0p[(cb0 + nt * 8) & 127];                        \
            uint32_t b1_ = r1p[(cb1 + nt * 8) & 127];                        \
            mma_tf32(ACC[0][nt][0], ACC[0][nt][1], ACC[0][nt][2], ACC[0][nt][3], \
                     af[0][kt][0], af[0][kt][1], af[0][kt][2], af[0][kt][3], b0_, b1_); \
            mma_tf32(ACC[1][nt][0], ACC[1][nt][1], ACC[1][nt][2], ACC[1][nt][3], \
                     af[1][kt][0], af[1][kt][1], af[1][kt][2], af[1][kt][3], b0_, b1_); \
        }                                                                    \
    }                                                                        \
} while (0)

// pipelined stage: wait prefetched group, sync, prefetch next, mma current
#define STAGE(NEXTSRC, NEXTDSTU, CURBUF, ACC) do {                           \
    asm volatile("cp.async.wait_group 0;\n" ::: "memory");                   \
    __syncthreads();                                                         \
    { const uint32_t* _ns = (NEXTSRC); if (_ns) ISSUE(_ns, NEXTDSTU); }      \
    MMA_LOOP32(CURBUF, ACC);                                                 \
} while (0)

#define LOAD_AF_F32(CB) do {                                                 \
    _Pragma("unroll")                                                        \
    for (int mt = 0; mt < 2; ++mt)                                           \
    _Pragma("unroll")                                                        \
    for (int kt = 0; kt < 8; ++kt) {                                         \
        const float* ap = qs + (r0m + mt * 16 + qr) * QS + (CB) + kt * 8 + ql; \
        af[mt][kt][0] = f2tf(ap[0]);                                         \
        af[mt][kt][1] = f2tf(ap[8 * QS]);                                    \
        af[mt][kt][2] = f2tf(ap[4]);                                         \
        af[mt][kt][3] = f2tf(ap[8 * QS + 4]);                                \
    }                                                                        \
} while (0)

#define LOAD_AF_BITS(CB) do {                                                \
    _Pragma("unroll")                                                        \
    for (int mt = 0; mt < 2; ++mt)                                           \
    _Pragma("unroll")                                                        \
    for (int kt = 0; kt < 8; ++kt) {                                         \
        const uint32_t* ap = qsu + (r0m + mt * 16 + qr) * QS + (CB) + kt * 8 + ql; \
        af[mt][kt][0] = ap[0];                                               \
        af[mt][kt][1] = ap[8 * QS];                                          \
        af[mt][kt][2] = ap[4];                                               \
        af[mt][kt][3] = ap[8 * QS + 4];                                      \
    }                                                                        \
} while (0)

// ---------------- main fused kernel: one CTA per window ----------------
__global__ void __launch_bounds__(THREADS, 1)
swin_block_kernel(const float* __restrict__ x,
                  const float* __restrict__ qb, const float* __restrict__ kb,
                  const float* __restrict__ vb, const float* __restrict__ pb,
                  const float* __restrict__ ls, float* __restrict__ out)
{
    extern __shared__ float sm[];
    float* qs  = sm;
    float* kss = sm + NTOK * QS;
    float* vsm = sm + 2 * NTOK * QS;
    const uint32_t* qsu = (const uint32_t*)qs;
    uint32_t* qsw = (uint32_t*)qs;
    uint32_t* vsw = (uint32_t*)vsm;

    const int b    = blockIdx.x;
    const int tid  = threadIdx.x;
    const int warp = tid >> 5;
    const int lane = tid & 31;
    const int r0m  = (warp & 1) * 32;       // warp row-tile base (2 mtiles of 16)
    const int n0   = (warp >> 1) * 32;      // warp col-tile base (4 ntiles of 8)
    const int qr   = lane >> 2;             // quad row 0..7
    const int ql   = lane & 3;              // quad col 0..3
    const int ldrow = tid >> 5;             // staging row base 0..7
    const int ldcol = (tid & 31) * 4;       // staging col 0..124
    const int sdcol = (ldcol + 4 * ldrow) & 127;   // swizzled staging dst col
    const int cb0  = n0 + qr + 4 * ql;      // swizzled B-frag col base (b0)
    const int cb1  = cb0 + 16;              // (b1: row+4 -> shift +16)

    const uint32_t vsm_u = (uint32_t)__cvta_generic_to_shared(vsm);
    const uint32_t kss_u = (uint32_t)__cvta_generic_to_shared(kss);

    uint32_t af[2][8][4];

    // prefetch stage 0 (qw s0 hf0) into vsm strip
    ISSUE(WSRC(0, 0, 0), BUF_ADR(0));

    // load x [64][256] into qs (fp32, stride QS)
    const float* xg = x + (size_t)b * (NTOK * CDIM);
    for (int t = tid; t < 64 * 64; t += THREADS) {
        int i = t >> 6, c4 = t & 63;
        *(float4*)&qs[i * QS + c4 * 4] = ((const float4*)xg)[i * 64 + c4];
    }
    __syncthreads();   // x visible to ALL warps before any A-fragment load

    // =========== Phase 1: QKV dual-branch residual linears ===========
#pragma unroll
    for (int s = 0; s < 2; ++s) {
        float accQ[2][4][4], accK[2][4][4], accV[2][4][4];
#pragma unroll
        for (int mt = 0; mt < 2; ++mt)
#pragma unroll
            for (int nt = 0; nt < 4; ++nt)
#pragma unroll
                for (int e = 0; e < 4; ++e) {
                    accQ[mt][nt][e] = 0.f; accK[mt][nt][e] = 0.f; accV[mt][nt][e] = 0.f;
                }

#pragma unroll
        for (int hf = 0; hf < 2; ++hf) {
            LOAD_AF_F32(s * 128 + hf * 64);
            const int t0 = (s * 2 + hf) * 3;
            STAGE(WSRC(1, s, hf), BUF_ADR(t0 + 1), BUF_PTR(t0 + 0), accQ);
            STAGE(WSRC(2, s, hf), BUF_ADR(t0 + 2), BUF_PTR(t0 + 1), accK);
            const uint32_t* nxt = (hf == 0) ? WSRC(0, s, 1)
                                : (s == 0)  ? WSRC(0, 1, 0) : (const uint32_t*)0;
            STAGE(nxt, BUF_ADR(t0 + 3 < 12 ? t0 + 3 : 0), BUF_PTR(t0 + 2), accV);
        }
        __syncthreads();   // all mma reads of staged weights done before epilogue writes

        // epilogue: residual + bias; k,q fp32 (normalized later), v tf32 bits SWIZZLED
#pragma unroll
        for (int mt = 0; mt < 2; ++mt) {
            const int rr = r0m + mt * 16 + qr;
            const float* x0p = qs + rr * QS + s * 128;
            const float* x1p = x0p + 8 * QS;
#pragma unroll
            for (int nt = 0; nt < 4; ++nt) {
                const int c = n0 + nt * 8 + 2 * ql;       // col within half (<=126)
                const int vc = (c + 4 * qr) & 127;        // swizzled v col (even)
                float2 x0 = *(const float2*)&x0p[c];
                float2 x1 = *(const float2*)&x1p[c];
                float2 kb2 = *(const float2*)&kb[s * 128 + c];
                float2 vb2 = *(const float2*)&vb[s * 128 + c];
                float2 qb2 = *(const float2*)&qb[s * 128 + c];
                *(float2*)&kss[rr * QS + s * 128 + c] =
                    make_float2(x0.x + accK[mt][nt][0] + kb2.x, x0.y + accK[mt][nt][1] + kb2.y);
                *(float2*)&kss[(rr + 8) * QS + s * 128 + c] =
                    make_float2(x1.x + accK[mt][nt][2] + kb2.x, x1.y + accK[mt][nt][3] + kb2.y);
                *(uint2*)&vsw[rr * QS + s * 128 + vc] =
                    make_uint2(f2tf(x0.x + accV[mt][nt][0] + vb2.x), f2tf(x0.y + accV[mt][nt][1] + vb2.y));
                *(uint2*)&vsw[(rr + 8) * QS + s * 128 + vc] =
                    make_uint2(f2tf(x1.x + accV[mt][nt][2] + vb2.x), f2tf(x1.y + accV[mt][nt][3] + vb2.y));
                *(float2*)&qs[rr * QS + s * 128 + c] =
                    make_float2(x0.x + accQ[mt][nt][0] + qb2.x, x0.y + accQ[mt][nt][1] + qb2.y);
                *(float2*)&qs[(rr + 8) * QS + s * 128 + c] =
                    make_float2(x1.x + accQ[mt][nt][2] + qb2.x, x1.y + accQ[mt][nt][3] + qb2.y);
            }
        }
        __syncthreads();
    }

    // =========== Phase 2: l2-normalize q,k; fold logit scale; store tf32 bits ===========
#pragma unroll
    for (int t4 = 0; t4 < 4; ++t4) {
        int t = tid + t4 * THREADS;      // 1024 tasks
        int bufsel = t >> 9;
        int h = (t >> 6) & 7;
        int i = t & 63;
        float* base = (bufsel ? kss : qs) + i * QS + h * HD;
        uint32_t* baseu = (uint32_t*)base;
        float4 vv[8];
        float ssq = 0.f;
#pragma unroll
        for (int u = 0; u < 8; ++u) {
            vv[u] = ((float4*)base)[u];
            ssq = fmaf(vv[u].x, vv[u].x, ssq);
            ssq = fmaf(vv[u].y, vv[u].y, ssq);
            ssq = fmaf(vv[u].z, vv[u].z, ssq);
            ssq = fmaf(vv[u].w, vv[u].w, ssq);
        }
        float inv = 1.f / fmaxf(sqrtf(ssq), 1e-12f);
        if (bufsel == 0) inv *= fminf(expf(ls[h]), 100.f);
#pragma unroll
        for (int u = 0; u < 8; ++u) {
            uint4 st;
            st.x = f2tf(vv[u].x * inv); st.y = f2tf(vv[u].y * inv);
            st.z = f2tf(vv[u].z * inv); st.w = f2tf(vv[u].w * inv);
            ((uint4*)baseu)[u] = st;
        }
    }
    __syncthreads();

    // =========== Phase 3: attention via tf32 mma, one warp per head ===========
    {
        const int h = warp;
        const float* Tw = d_Tcomb + (size_t)(((b & (NWIN - 1)) * NHEADS + h) << 12);
        const int s0l = (lane & ~3) | (ql >> 1);
        const bool odd = ql & 1;
        const uint32_t* vbase = (const uint32_t*)vsm + (h >> 2) * 128;   // half base
        const int vc0 = (h & 3) * 32 + qr + 4 * ql;                      // swizzled V col base

#pragma unroll 1
        for (int mt = 0; mt < 4; ++mt) {
            const int i0r = mt * 16 + qr;

            uint32_t qa[4][4];
#pragma unroll
            for (int kt = 0; kt < 4; ++kt) {
                const uint32_t* ap = qsu + i0r * QS + h * HD + kt * 8 + ql;
                qa[kt][0] = ap[0];
                qa[kt][1] = ap[8 * QS];
                qa[kt][2] = ap[4];
                qa[kt][3] = ap[8 * QS + 4];
            }

            float S[8][4];
#pragma unroll
            for (int nt = 0; nt < 8; ++nt) { S[nt][0] = S[nt][1] = S[nt][2] = S[nt][3] = 0.f; }
#pragma unroll
            for (int kt = 0; kt < 4; ++kt) {
#pragma unroll
                for (int nt = 0; nt < 8; ++nt) {
                    const uint32_t* kp = (const uint32_t*)kss + (nt * 8 + qr) * QS + h * HD + kt * 8 + ql;
                    mma_tf32(S[nt][0], S[nt][1], S[nt][2], S[nt][3],
                             qa[kt][0], qa[kt][1], qa[kt][2], qa[kt][3], kp[0], kp[4]);
                }
            }

            float rmax0 = -1e30f, rmax1 = -1e30f;
#pragma unroll
            for (int nt = 0; nt < 8; ++nt) {
                float2 t0 = *(const float2*)&Tw[i0r * 64 + nt * 8 + 2 * ql];
                float2 t1 = *(const float2*)&Tw[(i0r + 8) * 64 + nt * 8 + 2 * ql];
                S[nt][0] += t0.x; S[nt][1] += t0.y;
                S[nt][2] += t1.x; S[nt][3] += t1.y;
                rmax0 = fmaxf(rmax0, fmaxf(S[nt][0], S[nt][1]));
                rmax1 = fmaxf(rmax1, fmaxf(S[nt][2], S[nt][3]));
            }
            rmax0 = fmaxf(rmax0, __shfl_xor_sync(0xffffffffu, rmax0, 1));
            rmax0 = fmaxf(rmax0, __shfl_xor_sync(0xffffffffu, rmax0, 2));
            rmax1 = fmaxf(rmax1, __shfl_xor_sync(0xffffffffu, rmax1, 1));
            rmax1 = fmaxf(rmax1, __shfl_xor_sync(0xffffffffu, rmax1, 2));

            float sum0 = 0.f, sum1 = 0.f;
#pragma unroll
            for (int nt = 0; nt < 8; ++nt) {
                S[nt][0] = __expf(S[nt][0] - rmax0); sum0 += S[nt][0];
                S[nt][1] = __expf(S[nt][1] - rmax0); sum0 += S[nt][1];
                S[nt][2] = __expf(S[nt][2] - rmax1); sum1 += S[nt][2];
                S[nt][3] = __expf(S[nt][3] - rmax1); sum1 += S[nt][3];
            }
            sum0 += __shfl_xor_sync(0xffffffffu, sum0, 1);
            sum0 += __shfl_xor_sync(0xffffffffu, sum0, 2);
            sum1 += __shfl_xor_sync(0xffffffffu, sum1, 1);
            sum1 += __shfl_xor_sync(0xffffffffu, sum1, 2);
            float inv0 = 1.f / sum0, inv1 = 1.f / sum1;

            uint32_t pa[8][4];
#pragma unroll
            for (int nt = 0; nt < 8; ++nt) {
                uint32_t u0 = f2tf(S[nt][0]), u1 = f2tf(S[nt][1]);
                uint32_t u2 = f2tf(S[nt][2]), u3 = f2tf(S[nt][3]);
                uint32_t v0 = __shfl_sync(0xffffffffu, u0, s0l);
                uint32_t v1 = __shfl_sync(0xffffffffu, u1, s0l);
                pa[nt][0] = odd ? v1 : v0;
                uint32_t v2 = __shfl_sync(0xffffffffu, u2, s0l);
                uint32_t v3 = __shfl_sync(0xffffffffu, u3, s0l);
                pa[nt][1] = odd ? v3 : v2;
                v0 = __shfl_sync(0xffffffffu, u0, s0l + 2);
                v1 = __shfl_sync(0xffffffffu, u1, s0l + 2);
                pa[nt][2] = odd ? v1 : v0;
                v2 = __shfl_sync(0xffffffffu, u2, s0l + 2);
                v3 = __shfl_sync(0xffffffffu, u3, s0l + 2);
                pa[nt][3] = odd ? v3 : v2;
            }

            float O[4][4];
#pragma unroll
            for (int nd = 0; nd < 4; ++nd) { O[nd][0] = O[nd][1] = O[nd][2] = O[nd][3] = 0.f; }
#pragma unroll
            for (int kt = 0; kt < 8; ++kt) {
                const uint32_t* rA = vbase + (kt * 8 + ql) * QS;
                const uint32_t* rB = vbase + (kt * 8 + ql + 4) * QS;
#pragma unroll
                for (int nd = 0; nd < 4; ++nd) {
                    uint32_t b0 = rA[(vc0 + nd * 8) & 127];
                    uint32_t b1 = rB[(vc0 + 16 + nd * 8) & 127];
                    mma_tf32(O[nd][0], O[nd][1], O[nd][2], O[nd][3],
                             pa[kt][0], pa[kt][1], pa[kt][2], pa[kt][3], b0, b1);
                }
            }

#pragma unroll
            for (int nd = 0; nd < 4; ++nd) {
                uint2 st0, st1;
                st0.x = f2tf(O[nd][0] * inv0); st0.y = f2tf(O[nd][1] * inv0);
                st1.x = f2tf(O[nd][2] * inv1); st1.y = f2tf(O[nd][3] * inv1);
                *(uint2*)&qsw[i0r * QS + h * HD + nd * 8 + 2 * ql] = st0;
                *(uint2*)&qsw[(i0r + 8) * QS + h * HD + nd * 8 + 2 * ql] = st1;
            }
        }
    }
    __syncthreads();   // all O (tf32 bits) written; vsm/kss now dead

    // =========== Phase 4: output projection, store to gmem ===========
    float* og = out + (size_t)b * (NTOK * CDIM);
    ISSUE(WSRC(3, 0, 0), BUF_ADR(12));     // prefetch first proj stage
#pragma unroll
    for (int s = 0; s < 2; ++s) {
        float accP[2][4][4];
#pragma unroll
        for (int mt = 0; mt < 2; ++mt)
#pragma unroll
            for (int nt = 0; nt < 4; ++nt)
#pragma unroll
                for (int e = 0; e < 4; ++e) accP[mt][nt][e] = 0.f;

#pragma unroll
        for (int hf = 0; hf < 2; ++hf) {
            LOAD_AF_BITS(s * 128 + hf * 64);
            const int t = 12 + s * 2 + hf;
            const uint32_t* nxt = (t < 15) ? WSRC(3, (t - 11) >> 1, (t - 11) & 1)
                                           : (const uint32_t*)0;
            STAGE(nxt, BUF_ADR((t + 1) & 15), BUF_PTR(t), accP);
        }
#pragma unroll
        for (int mt = 0; mt < 2; ++mt) {
            const int rr = r0m + mt * 16 + qr;
#pragma unroll
            for (int nt = 0; nt < 4; ++nt) {
                const int c = n0 + nt * 8 + 2 * ql;
                float2 pb2 = *(const float2*)&pb[s * 128 + c];
                *(float2*)&og[rr * CDIM + s * 128 + c] =
                    make_float2(accP[mt][nt][0] + pb2.x, accP[mt][nt][1] + pb2.y);
                *(float2*)&og[(rr + 8) * CDIM + s * 128 + c] =
                    make_float2(accP[mt][nt][2] + pb2.x, accP[mt][nt][3] + pb2.y);
            }
        }
    }
}

extern "C" void kernel_launch(void* const* d_in, const int* in_sizes, int n_in,
                              void* d_out, int out_size) {
    const float* x    = (const float*)d_in[0];
    const float* mask = (const float*)d_in[1];
    const float* qw   = (const float*)d_in[2];
    const float* qb   = (const float*)d_in[3];
    const float* kw   = (const float*)d_in[4];
    const float* kb   = (const float*)d_in[5];
    const float* vw   = (const float*)d_in[6];
    const float* vb   = (const float*)d_in[7];
    const float* pw   = (const float*)d_in[8];
    const float* pb   = (const float*)d_in[9];
    const float* w1   = (const float*)d_in[10];
    const float* b1   = (const float*)d_in[11];
    const float* w2   = (const float*)d_in[12];
    const float* ls   = (const float*)d_in[13];
    const float* rpb  = (const float*)d_in[14];
    const int*   rpi  = (const int*)d_in[15];
    float* out = (float*)d_out;

    static bool inited = false;
    if (!inited) {
        cudaFuncSetAttribute(swin_block_kernel,
                             cudaFuncAttributeMaxDynamicSharedMemorySize, SMEM_BYTES);
        inited = true;
    }

    wconv_kernel<<<512, 256>>>(qw, kw, vw, pw);
    cpb_mlp_kernel<<<225, 128>>>(rpb, w1, b1, w2);
    bias_combine_kernel<<<(NWIN * NHEADS * NTOK * NTOK + 255) / 256, 256>>>(rpi, mask);
    swin_block_kernel<<<NBATCH, THREADS, SMEM_BYTES>>>(x, qb, kb, vb, pb, ls, out);
}

// round 9
// speedup vs baseline: 1.3463x; 1.3463x over previous
#include <cuda_runtime.h>
#include <math.h>
#include <stdint.h>

#define NTOK 64
#define CDIM 256
#define NHEADS 8
#define HD   32
#define QS   260          // row stride (floats) for q/k/v smem buffers
#define NWIN 64
#define NBATCH 2048
#define THREADS 256

#define SMEM_FLOATS (3 * NTOK * QS)
#define SMEM_BYTES  (SMEM_FLOATS * 4)     // 199680 B

__device__ float d_tbl2[225 * NHEADS];
__device__ float d_Tcomb[NWIN * NHEADS * NTOK * NTOK];   // 16*sigmoid(bias)+mask, 8MB
__device__ uint32_t d_wtf[4 * 32768];                    // q,k,v,p weights as tf32 bits

// ---------------- prologue 0: weights -> tf32 bits ----------------
__device__ __forceinline__ uint32_t f2tf(float f) {
    uint32_t u; asm("cvt.rna.tf32.f32 %0, %1;" : "=r"(u) : "f"(f)); return u;
}

__global__ void wconv_kernel(const float* __restrict__ qw, const float* __restrict__ kw,
                             const float* __restrict__ vw, const float* __restrict__ pw) {
    int idx = blockIdx.x * blockDim.x + threadIdx.x;
    if (idx >= 4 * 32768) return;
    int sel = idx >> 15, off = idx & 32767;
    float v = (sel == 0) ? qw[off] : (sel == 1) ? kw[off] : (sel == 2) ? vw[off] : pw[off];
    d_wtf[idx] = f2tf(v);
}

// ---------------- prologue 1: rpb_table -> MLP -> (225, 8) ----------------
__global__ void cpb_mlp_kernel(const float* __restrict__ rpb,
                               const float* __restrict__ w1,
                               const float* __restrict__ b1,
                               const float* __restrict__ w2) {
    __shared__ float acc[NHEADS];
    int p = blockIdx.x;          // 0..224
    int j = threadIdx.x;         // 0..127
    if (j < NHEADS) acc[j] = 0.f;
    __syncthreads();
    float t0 = rpb[p * 2 + 0];
    float t1 = rpb[p * 2 + 1];
    float hid = fmaxf(t0 * w1[j] + t1 * w1[128 + j] + b1[j], 0.f);
#pragma unroll
    for (int h = 0; h < NHEADS; ++h) {
        float pv = hid * w2[j * 8 + h];
#pragma unroll
        for (int o = 16; o; o >>= 1) pv += __shfl_xor_sync(0xffffffffu, pv, o);
        if ((j & 31) == 0) atomicAdd(&acc[h], pv);
    }
    __syncthreads();
    if (j < NHEADS) d_tbl2[p * 8 + j] = acc[j];
}

// ---------------- prologue 2: combined bias+mask table ----------------
__global__ void bias_combine_kernel(const int* __restrict__ rpi,
                                    const float* __restrict__ mask) {
    int idx = blockIdx.x * blockDim.x + threadIdx.x;
    if (idx >= NWIN * NHEADS * NTOK * NTOK) return;
    int ij = idx & 4095;
    int h  = (idx >> 12) & 7;
    int w  = idx >> 15;
    float bv = d_tbl2[rpi[ij] * 8 + h];
    d_Tcomb[idx] = 16.f / (1.f + expf(-bv)) + mask[w * 4096 + ij];
}

// ---------------- mma helper ----------------
__device__ __forceinline__ void mma_tf32(float& d0, float& d1, float& d2, float& d3,
                                         uint32_t a0, uint32_t a1, uint32_t a2, uint32_t a3,
                                         uint32_t b0, uint32_t b1) {
    asm volatile(
        "mma.sync.aligned.m16n8k8.row.col.f32.tf32.tf32.f32 "
        "{%0,%1,%2,%3},{%4,%5,%6,%7},{%8,%9},{%0,%1,%2,%3};"
        : "+f"(d0), "+f"(d1), "+f"(d2), "+f"(d3)
        : "r"(a0), "r"(a1), "r"(a2), "r"(a3), "r"(b0), "r"(b1));
}

// weight source in d_wtf: w 0..3 = q,k,v,p
#define WSRC(w, s, hf) (d_wtf + (w) * 32768 + (s) * 16384 + (hf) * 8192)

// stage buffer for stage index T (compile-time literal after unrolling):
// even -> vsm strip, odd -> kss strip; col region 128 for stages 6..11
#define BUF_PTR(T) ((const uint32_t*)((((T) & 1) ? (void*)kss : (void*)vsm)) + \
                    ((((T) >= 6) && ((T) < 12)) ? 128 : 0))
#define BUF_ADR(T) (((((T) & 1) ? kss_u : vsm_u)) + ((((T) >= 6) && ((T) < 12)) ? 512u : 0u))

// issue the 8 cp.async for one [64][128] weight stage + commit
#define ISSUE(SRC, DSTU) do {                                                \
    const uint32_t* _s0 = (SRC) + ldrow * 128 + ldcol;                       \
    uint32_t _d0 = (DSTU) + (uint32_t)((ldrow * QS + ldcol) * 4);            \
    _Pragma("unroll")                                                        \
    for (int k_ = 0; k_ < 8; ++k_)                                           \
        asm volatile("cp.async.cg.shared.global [%0], [%1], 16;\n"           \
            :: "r"(_d0 + (uint32_t)(k_ * 8 * QS * 4)),                       \
               "l"(_s0 + k_ * 8 * 128) : "memory");                          \
    asm volatile("cp.async.commit_group;\n" ::: "memory");                   \
} while (0)

// 32x32 warp-tile mma over one staged [64 K][128 N] weight tile
#define MMA_LOOP32(BUFP, ACC) do {                                           \
    const uint32_t* _bu = (BUFP);                                            \
    _Pragma("unroll")                                                        \
    for (int kt = 0; kt < 8; ++kt) {                                         \
        const uint32_t* bp = _bu + (kt * 8 + ql) * QS + n0 + qr;             \
        _Pragma("unroll")                                                    \
        for (int nt = 0; nt < 4; ++nt) {                                     \
            uint32_t b0_ = bp[nt * 8], b1_ = bp[4 * QS + nt * 8];            \
            mma_tf32(ACC[0][nt][0], ACC[0][nt][1], ACC[0][nt][2], ACC[0][nt][3], \
                     af[0][kt][0], af[0][kt][1], af[0][kt][2], af[0][kt][3], b0_, b1_); \
            mma_tf32(ACC[1][nt][0], ACC[1][nt][1], ACC[1][nt][2], ACC[1][nt][3], \
                     af[1][kt][0], af[1][kt][1], af[1][kt][2], af[1][kt][3], b0_, b1_); \
        }                                                                    \
    }                                                                        \
} while (0)

// pipelined stage: wait prefetched group, sync, prefetch next, mma current
#define STAGE(NEXTSRC, NEXTDSTU, CURBUF, ACC) do {                           \
    asm volatile("cp.async.wait_group 0;\n" ::: "memory");                   \
    __syncthreads();                                                         \
    { const uint32_t* _ns = (NEXTSRC); if (_ns) ISSUE(_ns, NEXTDSTU); }      \
    MMA_LOOP32(CURBUF, ACC);                                                 \
} while (0)

#define LOAD_AF_F32(CB) do {                                                 \
    _Pragma("unroll")                                                        \
    for (int mt = 0; mt < 2; ++mt)                                           \
    _Pragma("unroll")                                                        \
    for (int kt = 0; kt < 8; ++kt) {                                         \
        const float* ap = qs + (r0m + mt * 16 + qr) * QS + (CB) + kt * 8 + ql; \
        af[mt][kt][0] = f2tf(ap[0]);                                         \
        af[mt][kt][1] = f2tf(ap[8 * QS]);                                    \
        af[mt][kt][2] = f2tf(ap[4]);                                         \
        af[mt][kt][3] = f2tf(ap[8 * QS + 4]);                                \
    }                                                                        \
} while (0)

#define LOAD_AF_BITS(CB) do {                                                \
    _Pragma("unroll")                                                        \
    for (int mt = 0; mt < 2; ++mt)                                           \
    _Pragma("unroll")                                                        \
    for (int kt = 0; kt < 8; ++kt) {                                         \
        const uint32_t* ap = qsu + (r0m + mt * 16 + qr) * QS + (CB) + kt * 8 + ql; \
        af[mt][kt][0] = ap[0];                                               \
        af[mt][kt][1] = ap[8 * QS];                                          \
        af[mt][kt][2] = ap[4];                                               \
        af[mt][kt][3] = ap[8 * QS + 4];                                      \
    }                                                                        \
} while (0)

// ---------------- main fused kernel: one CTA per window ----------------
__global__ void __launch_bounds__(THREADS, 1)
swin_block_kernel(const float* __restrict__ x,
                  const float* __restrict__ qb, const float* __restrict__ kb,
                  const float* __restrict__ vb, const float* __restrict__ pb,
                  const float* __restrict__ ls, float* __restrict__ out)
{
    extern __shared__ float sm[];
    float* qs  = sm;
    float* kss = sm + NTOK * QS;
    float* vsm = sm + 2 * NTOK * QS;
    const uint32_t* qsu = (const uint32_t*)qs;
    uint32_t* qsw = (uint32_t*)qs;
    uint32_t* vsw = (uint32_t*)vsm;

    const int b    = blockIdx.x;
    const int tid  = threadIdx.x;
    const int warp = tid >> 5;
    const int lane = tid & 31;
    const int r0m  = (warp & 1) * 32;       // warp row-tile base (2 mtiles of 16)
    const int n0   = (warp >> 1) * 32;      // warp col-tile base (4 ntiles of 8)
    const int qr   = lane >> 2;             // quad row 0..7
    const int ql   = lane & 3;              // quad col 0..3
    const int ldrow = tid >> 5;             // staging row base 0..7
    const int ldcol = (tid & 31) * 4;       // staging col 0..124

    const uint32_t vsm_u = (uint32_t)__cvta_generic_to_shared(vsm);
    const uint32_t kss_u = (uint32_t)__cvta_generic_to_shared(kss);

    uint32_t af[2][8][4];

    // prefetch stage 0 (qw s0 hf0) into vsm strip
    ISSUE(WSRC(0, 0, 0), BUF_ADR(0));

    // load x [64][256] into qs (fp32, stride QS)
    const float* xg = x + (size_t)b * (NTOK * CDIM);
    for (int t = tid; t < 64 * 64; t += THREADS) {
        int i = t >> 6, c4 = t & 63;
        *(float4*)&qs[i * QS + c4 * 4] = ((const float4*)xg)[i * 64 + c4];
    }
    __syncthreads();   // x visible to ALL warps before any A-fragment load

    // =========== Phase 1: QKV dual-branch residual linears ===========
#pragma unroll
    for (int s = 0; s < 2; ++s) {
        float accQ[2][4][4], accK[2][4][4], accV[2][4][4];
#pragma unroll
        for (int mt = 0; mt < 2; ++mt)
#pragma unroll
            for (int nt = 0; nt < 4; ++nt)
#pragma unroll
                for (int e = 0; e < 4; ++e) {
                    accQ[mt][nt][e] = 0.f; accK[mt][nt][e] = 0.f; accV[mt][nt][e] = 0.f;
                }

#pragma unroll
        for (int hf = 0; hf < 2; ++hf) {
            LOAD_AF_F32(s * 128 + hf * 64);
            const int t0 = (s * 2 + hf) * 3;
            STAGE(WSRC(1, s, hf), BUF_ADR(t0 + 1), BUF_PTR(t0 + 0), accQ);
            STAGE(WSRC(2, s, hf), BUF_ADR(t0 + 2), BUF_PTR(t0 + 1), accK);
            const uint32_t* nxt = (hf == 0) ? WSRC(0, s, 1)
                                : (s == 0)  ? WSRC(0, 1, 0) : (const uint32_t*)0;
            STAGE(nxt, BUF_ADR(t0 + 3 < 12 ? t0 + 3 : 0), BUF_PTR(t0 + 2), accV);
        }
        __syncthreads();   // all mma reads of staged weights done before epilogue writes

        // epilogue: residual + bias; k,q fp32 (normalized later), v as tf32 bits
#pragma unroll
        for (int mt = 0; mt < 2; ++mt) {
            const int rr = r0m + mt * 16 + qr;
            const float* x0p = qs + rr * QS + s * 128;
            const float* x1p = x0p + 8 * QS;
#pragma unroll
            for (int nt = 0; nt < 4; ++nt) {
                const int c = n0 + nt * 8 + 2 * ql;
                float2 x0 = *(const float2*)&x0p[c];
                float2 x1 = *(const float2*)&x1p[c];
                float2 kb2 = *(const float2*)&kb[s * 128 + c];
                float2 vb2 = *(const float2*)&vb[s * 128 + c];
                float2 qb2 = *(const float2*)&qb[s * 128 + c];
                *(float2*)&kss[rr * QS + s * 128 + c] =
                    make_float2(x0.x + accK[mt][nt][0] + kb2.x, x0.y + accK[mt][nt][1] + kb2.y);
                *(float2*)&kss[(rr + 8) * QS + s * 128 + c] =
                    make_float2(x1.x + accK[mt][nt][2] + kb2.x, x1.y + accK[mt][nt][3] + kb2.y);
                *(uint2*)&vsw[rr * QS + s * 128 + c] =
                    make_uint2(f2tf(x0.x + accV[mt][nt][0] + vb2.x), f2tf(x0.y + accV[mt][nt][1] + vb2.y));
                *(uint2*)&vsw[(rr + 8) * QS + s * 128 + c] =
                    make_uint2(f2tf(x1.x + accV[mt][nt][2] + vb2.x), f2tf(x1.y + accV[mt][nt][3] + vb2.y));
                *(float2*)&qs[rr * QS + s * 128 + c] =
                    make_float2(x0.x + accQ[mt][nt][0] + qb2.x, x0.y + accQ[mt][nt][1] + qb2.y);
                *(float2*)&qs[(rr + 8) * QS + s * 128 + c] =
                    make_float2(x1.x + accQ[mt][nt][2] + qb2.x, x1.y + accQ[mt][nt][3] + qb2.y);
            }
        }
        __syncthreads();
    }

    // =========== Phase 2: l2-normalize q,k; fold logit scale; store tf32 bits ===========
#pragma unroll
    for (int t4 = 0; t4 < 4; ++t4) {
        int t = tid + t4 * THREADS;      // 1024 tasks
        int bufsel = t >> 9;
        int h = (t >> 6) & 7;
        int i = t & 63;
        float* base = (bufsel ? kss : qs) + i * QS + h * HD;
        uint32_t* baseu = (uint32_t*)base;
        float4 vv[8];
        float ssq = 0.f;
#pragma unroll
        for (int u = 0; u < 8; ++u) {
            vv[u] = ((float4*)base)[u];
            ssq = fmaf(vv[u].x, vv[u].x, ssq);
            ssq = fmaf(vv[u].y, vv[u].y, ssq);
            ssq = fmaf(vv[u].z, vv[u].z, ssq);
            ssq = fmaf(vv[u].w, vv[u].w, ssq);
        }
        float inv = 1.f / fmaxf(sqrtf(ssq), 1e-12f);
        if (bufsel == 0) inv *= fminf(expf(ls[h]), 100.f);
#pragma unroll
        for (int u = 0; u < 8; ++u) {
            uint4 st;
            st.x = f2tf(vv[u].x * inv); st.y = f2tf(vv[u].y * inv);
            st.z = f2tf(vv[u].z * inv); st.w = f2tf(vv[u].w * inv);
            ((uint4*)baseu)[u] = st;
        }
    }
    __syncthreads();

    // =========== Phase 3: attention via tf32 mma, one warp per head ===========
    {
        const int h = warp;
        const float* Tw = d_Tcomb + (size_t)(((b & (NWIN - 1)) * NHEADS + h) << 12);
        const int s0l = (lane & ~3) | (ql >> 1);
        const bool odd = ql & 1;

#pragma unroll 1
        for (int mt = 0; mt < 4; ++mt) {
            const int i0r = mt * 16 + qr;

            uint32_t qa[4][4];
#pragma unroll
            for (int kt = 0; kt < 4; ++kt) {
                const uint32_t* ap = qsu + i0r * QS + h * HD + kt * 8 + ql;
                qa[kt][0] = ap[0];
                qa[kt][1] = ap[8 * QS];
                qa[kt][2] = ap[4];
                qa[kt][3] = ap[8 * QS + 4];
            }

            float S[8][4];
#pragma unroll
            for (int nt = 0; nt < 8; ++nt) { S[nt][0] = S[nt][1] = S[nt][2] = S[nt][3] = 0.f; }
#pragma unroll
            for (int kt = 0; kt < 4; ++kt) {
#pragma unroll
                for (int nt = 0; nt < 8; ++nt) {
                    const uint32_t* kp = (const uint32_t*)kss + (nt * 8 + qr) * QS + h * HD + kt * 8 + ql;
                    mma_tf32(S[nt][0], S[nt][1], S[nt][2], S[nt][3],
                             qa[kt][0], qa[kt][1], qa[kt][2], qa[kt][3], kp[0], kp[4]);
                }
            }

            float rmax0 = -1e30f, rmax1 = -1e30f;
#pragma unroll
            for (int nt = 0; nt < 8; ++nt) {
                float2 t0 = *(const float2*)&Tw[i0r * 64 + nt * 8 + 2 * ql];
                float2 t1 = *(const float2*)&Tw[(i0r + 8) * 64 + nt * 8 + 2 * ql];
                S[nt][0] += t0.x; S[nt][1] += t0.y;
                S[nt][2] += t1.x; S[nt][3] += t1.y;
                rmax0 = fmaxf(rmax0, fmaxf(S[nt][0], S[nt][1]));
                rmax1 = fmaxf(rmax1, fmaxf(S[nt][2], S[nt][3]));
            }
            rmax0 = fmaxf(rmax0, __shfl_xor_sync(0xffffffffu, rmax0, 1));
            rmax0 = fmaxf(rmax0, __shfl_xor_sync(0xffffffffu, rmax0, 2));
            rmax1 = fmaxf(rmax1, __shfl_xor_sync(0xffffffffu, rmax1, 1));
            rmax1 = fmaxf(rmax1, __shfl_xor_sync(0xffffffffu, rmax1, 2));

            float sum0 = 0.f, sum1 = 0.f;
#pragma unroll
            for (int nt = 0; nt < 8; ++nt) {
                S[nt][0] = __expf(S[nt][0] - rmax0); sum0 += S[nt][0];
                S[nt][1] = __expf(S[nt][1] - rmax0); sum0 += S[nt][1];
                S[nt][2] = __expf(S[nt][2] - rmax1); sum1 += S[nt][2];
                S[nt][3] = __expf(S[nt][3] - rmax1); sum1 += S[nt][3];
            }
            sum0 += __shfl_xor_sync(0xffffffffu, sum0, 1);
            sum0 += __shfl_xor_sync(0xffffffffu, sum0, 2);
            sum1 += __shfl_xor_sync(0xffffffffu, sum1, 1);
            sum1 += __shfl_xor_sync(0xffffffffu, sum1, 2);
            float inv0 = 1.f / sum0, inv1 = 1.f / sum1;

            uint32_t pa[8][4];
#pragma unroll
            for (int nt = 0; nt < 8; ++nt) {
                uint32_t u0 = f2tf(S[nt][0]), u1 = f2tf(S[nt][1]);
                uint32_t u2 = f2tf(S[nt][2]), u3 = f2tf(S[nt][3]);
                uint32_t v0 = __shfl_sync(0xffffffffu, u0, s0l);
                uint32_t v1 = __shfl_sync(0xffffffffu, u1, s0l);
                pa[nt][0] = odd ? v1 : v0;
                uint32_t v2 = __shfl_sync(0xffffffffu, u2, s0l);
                uint32_t v3 = __shfl_sync(0xffffffffu, u3, s0l);
                pa[nt][1] = odd ? v3 : v2;
                v0 = __shfl_sync(0xffffffffu, u0, s0l + 2);
                v1 = __shfl_sync(0xffffffffu, u1, s0l + 2);
                pa[nt][2] = odd ? v1 : v0;
                v2 = __shfl_sync(0xffffffffu, u2, s0l + 2);
                v3 = __shfl_sync(0xffffffffu, u3, s0l + 2);
                pa[nt][3] = odd ? v3 : v2;
            }

            float O[4][4];
#pragma unroll
            for (int nd = 0; nd < 4; ++nd) { O[nd][0] = O[nd][1] = O[nd][2] = O[nd][3] = 0.f; }
#pragma unroll
            for (int kt = 0; kt < 8; ++kt) {
#pragma unroll
                for (int nd = 0; nd < 4; ++nd) {
                    const uint32_t* vp = (const uint32_t*)vsm + (kt * 8 + ql) * QS + h * HD + nd * 8 + qr;
                    mma_tf32(O[nd][0], O[nd][1], O[nd][2], O[nd][3],
                             pa[kt][0], pa[kt][1], pa[kt][2], pa[kt][3], vp[0], vp[4 * QS]);
                }
            }

#pragma unroll
            for (int nd = 0; nd < 4; ++nd) {
                uint2 st0, st1;
                st0.x = f2tf(O[nd][0] * inv0); st0.y = f2tf(O[nd][1] * inv0);
                st1.x = f2tf(O[nd][2] * inv1); st1.y = f2tf(O[nd][3] * inv1);
                *(uint2*)&qsw[i0r * QS + h * HD + nd * 8 + 2 * ql] = st0;
                *(uint2*)&qsw[(i0r + 8) * QS + h * HD + nd * 8 + 2 * ql] = st1;
            }
        }
    }
    __syncthreads();   // all O (tf32 bits) written; vsm/kss now dead

    // =========== Phase 4: output projection, store to gmem ===========
    float* og = out + (size_t)b * (NTOK * CDIM);
    ISSUE(WSRC(3, 0, 0), BUF_ADR(12));     // prefetch first proj stage
#pragma unroll
    for (int s = 0; s < 2; ++s) {
        float accP[2][4][4];
#pragma unroll
        for (int mt = 0; mt < 2; ++mt)
#pragma unroll
            for (int nt = 0; nt < 4; ++nt)
#pragma unroll
                for (int e = 0; e < 4; ++e) accP[mt][nt][e] = 0.f;

#pragma unroll
        for (int hf = 0; hf < 2; ++hf) {
            LOAD_AF_BITS(s * 128 + hf * 64);
            const int t = 12 + s * 2 + hf;
            const uint32_t* nxt = (t < 15) ? WSRC(3, (t - 11) >> 1, (t - 11) & 1)
                                           : (const uint32_t*)0;
            STAGE(nxt, BUF_ADR((t + 1) & 15), BUF_PTR(t), accP);
        }
#pragma unroll
        for (int mt = 0; mt < 2; ++mt) {
            const int rr = r0m + mt * 16 + qr;
#pragma unroll
            for (int nt = 0; nt < 4; ++nt) {
                const int c = n0 + nt * 8 + 2 * ql;
                float2 pb2 = *(const float2*)&pb[s * 128 + c];
                *(float2*)&og[rr * CDIM + s * 128 + c] =
                    make_float2(accP[mt][nt][0] + pb2.x, accP[mt][nt][1] + pb2.y);
                *(float2*)&og[(rr + 8) * CDIM + s * 128 + c] =
                    make_float2(accP[mt][nt][2] + pb2.x, accP[mt][nt][3] + pb2.y);
            }
        }
    }
}

extern "C" void kernel_launch(void* const* d_in, const int* in_sizes, int n_in,
                              void* d_out, int out_size) {
    const float* x    = (const float*)d_in[0];
    const float* mask = (const float*)d_in[1];
    const float* qw   = (const float*)d_in[2];
    const float* qb   = (const float*)d_in[3];
    const float* kw   = (const float*)d_in[4];
    const float* kb   = (const float*)d_in[5];
    const float* vw   = (const float*)d_in[6];
    const float* vb   = (const float*)d_in[7];
    const float* pw   = (const float*)d_in[8];
    const float* pb   = (const float*)d_in[9];
    const float* w1   = (const float*)d_in[10];
    const float* b1   = (const float*)d_in[11];
    const float* w2   = (const float*)d_in[12];
    const float* ls   = (const float*)d_in[13];
    const float* rpb  = (const float*)d_in[14];
    const int*   rpi  = (const int*)d_in[15];
    float* out = (float*)d_out;

    static bool inited = false;
    if (!inited) {
        cudaFuncSetAttribute(swin_block_kernel,
                             cudaFuncAttributeMaxDynamicSharedMemorySize, SMEM_BYTES);
        inited = true;
    }

    wconv_kernel<<<512, 256>>>(qw, kw, vw, pw);
    cpb_mlp_kernel<<<225, 128>>>(rpb, w1, b1, w2);
    bias_combine_kernel<<<(NWIN * NHEADS * NTOK * NTOK + 255) / 256, 256>>>(rpi, mask);
    swin_block_kernel<<<NBATCH, THREADS, SMEM_BYTES>>>(x, qb, kb, vb, pb, ls, out);
}

// round 10
// speedup vs baseline: 1.4650x; 1.0882x over previous
#include <cuda_runtime.h>
#include <math.h>
#include <stdint.h>

#define NTOK 64
#define CDIM 256
#define NHEADS 8
#define HD   32
#define QS   132          // row stride (floats); 132 % 32 == 4 -> conflict pattern as validated
#define NWIN 64
#define NBATCH 2048
#define THREADS 256

#define SMEM_FLOATS (3 * NTOK * QS)
#define SMEM_BYTES  (SMEM_FLOATS * 4)     // 101376 B -> 2 CTAs/SM

__device__ float d_tbl2[225 * NHEADS];
__device__ float d_Tcomb[NWIN * NHEADS * NTOK * NTOK];   // 16*sigmoid(bias)+mask, 8MB
__device__ uint32_t d_wtf[4 * 32768];                    // q,k,v,p weights as tf32 bits

// ---------------- prologue 0: weights -> tf32 bits ----------------
__device__ __forceinline__ uint32_t f2tf(float f) {
    uint32_t u; asm("cvt.rna.tf32.f32 %0, %1;" : "=r"(u) : "f"(f)); return u;
}

__global__ void wconv_kernel(const float* __restrict__ qw, const float* __restrict__ kw,
                             const float* __restrict__ vw, const float* __restrict__ pw) {
    int idx = blockIdx.x * blockDim.x + threadIdx.x;
    if (idx >= 4 * 32768) return;
    int sel = idx >> 15, off = idx & 32767;
    float v = (sel == 0) ? qw[off] : (sel == 1) ? kw[off] : (sel == 2) ? vw[off] : pw[off];
    d_wtf[idx] = f2tf(v);
}

// ---------------- prologue 1: rpb_table -> MLP -> (225, 8) ----------------
__global__ void cpb_mlp_kernel(const float* __restrict__ rpb,
                               const float* __restrict__ w1,
                               const float* __restrict__ b1,
                               const float* __restrict__ w2) {
    __shared__ float acc[NHEADS];
    int p = blockIdx.x;          // 0..224
    int j = threadIdx.x;         // 0..127
    if (j < NHEADS) acc[j] = 0.f;
    __syncthreads();
    float t0 = rpb[p * 2 + 0];
    float t1 = rpb[p * 2 + 1];
    float hid = fmaxf(t0 * w1[j] + t1 * w1[128 + j] + b1[j], 0.f);
#pragma unroll
    for (int h = 0; h < NHEADS; ++h) {
        float pv = hid * w2[j * 8 + h];
#pragma unroll
        for (int o = 16; o; o >>= 1) pv += __shfl_xor_sync(0xffffffffu, pv, o);
        if ((j & 31) == 0) atomicAdd(&acc[h], pv);
    }
    __syncthreads();
    if (j < NHEADS) d_tbl2[p * 8 + j] = acc[j];
}

// ---------------- prologue 2: combined bias+mask table ----------------
__global__ void bias_combine_kernel(const int* __restrict__ rpi,
                                    const float* __restrict__ mask) {
    int idx = blockIdx.x * blockDim.x + threadIdx.x;
    if (idx >= NWIN * NHEADS * NTOK * NTOK) return;
    int ij = idx & 4095;
    int h  = (idx >> 12) & 7;
    int w  = idx >> 15;
    float bv = d_tbl2[rpi[ij] * 8 + h];
    d_Tcomb[idx] = 16.f / (1.f + expf(-bv)) + mask[w * 4096 + ij];
}

// ---------------- mma helper ----------------
__device__ __forceinline__ void mma_tf32(float& d0, float& d1, float& d2, float& d3,
                                         uint32_t a0, uint32_t a1, uint32_t a2, uint32_t a3,
                                         uint32_t b0, uint32_t b1) {
    asm volatile(
        "mma.sync.aligned.m16n8k8.row.col.f32.tf32.tf32.f32 "
        "{%0,%1,%2,%3},{%4,%5,%6,%7},{%8,%9},{%0,%1,%2,%3};"
        : "+f"(d0), "+f"(d1), "+f"(d2), "+f"(d3)
        : "r"(a0), "r"(a1), "r"(a2), "r"(a3), "r"(b0), "r"(b1));
}

// weight source in d_wtf: w 0..3 = q,k,v,p ; per-branch half [64][128]
#define WSRC(w, hf) (d_wtf + (w) * 32768 + s * 16384 + (hf) * 8192)

// issue the 8 cp.async for one [64][128] weight stage + commit
#define ISSUE(SRC, DSTU) do {                                                \
    const uint32_t* _s0 = (SRC) + ldrow * 128 + ldcol;                       \
    uint32_t _d0 = (DSTU) + (uint32_t)((ldrow * QS + ldcol) * 4);            \
    _Pragma("unroll")                                                        \
    for (int k_ = 0; k_ < 8; ++k_)                                           \
        asm volatile("cp.async.cg.shared.global [%0], [%1], 16;\n"           \
            :: "r"(_d0 + (uint32_t)(k_ * 8 * QS * 4)),                       \
               "l"(_s0 + k_ * 8 * 128) : "memory");                          \
    asm volatile("cp.async.commit_group;\n" ::: "memory");                   \
} while (0)

#define WAITSYNC() do {                                                      \
    asm volatile("cp.async.wait_group 0;\n" ::: "memory");                   \
    __syncthreads();                                                         \
} while (0)

// 16x64 warp-tile mma over one staged [64 K][128 N] weight tile
#define MMA_LOOP(BUFP, ACC) do {                                             \
    const uint32_t* _bu = (const uint32_t*)(BUFP);                           \
    _Pragma("unroll")                                                        \
    for (int kt = 0; kt < 8; ++kt) {                                         \
        const uint32_t* bp = _bu + (kt * 8 + ql) * QS + n0 + qr;             \
        _Pragma("unroll")                                                    \
        for (int nt = 0; nt < 8; ++nt) {                                     \
            mma_tf32(ACC[nt][0], ACC[nt][1], ACC[nt][2], ACC[nt][3],         \
                     af[kt][0], af[kt][1], af[kt][2], af[kt][3],             \
                     bp[nt * 8], bp[4 * QS + nt * 8]);                       \
        }                                                                    \
    }                                                                        \
} while (0)

#define LOAD_AF_F32(CB) do {                                                 \
    _Pragma("unroll")                                                        \
    for (int kt = 0; kt < 8; ++kt) {                                         \
        const float* ap = qs + (r0 + qr) * QS + (CB) + kt * 8 + ql;          \
        af[kt][0] = f2tf(ap[0]);                                             \
        af[kt][1] = f2tf(ap[8 * QS]);                                        \
        af[kt][2] = f2tf(ap[4]);                                             \
        af[kt][3] = f2tf(ap[8 * QS + 4]);                                    \
    }                                                                        \
} while (0)

#define LOAD_AF_BITS(CB) do {                                                \
    _Pragma("unroll")                                                        \
    for (int kt = 0; kt < 8; ++kt) {                                         \
        const uint32_t* ap = qsu + (r0 + qr) * QS + (CB) + kt * 8 + ql;      \
        af[kt][0] = ap[0];                                                   \
        af[kt][1] = ap[8 * QS];                                              \
        af[kt][2] = ap[4];                                                   \
        af[kt][3] = ap[8 * QS + 4];                                          \
    }                                                                        \
} while (0)

#define ZERO_ACC(A) do {                                                     \
    _Pragma("unroll")                                                        \
    for (int nt = 0; nt < 8; ++nt)                                           \
        { A[nt][0] = 0.f; A[nt][1] = 0.f; A[nt][2] = 0.f; A[nt][3] = 0.f; }  \
} while (0)

// ---------------- main fused kernel: one CTA per (window, branch) ----------------
__global__ void __launch_bounds__(THREADS, 2)
swin_branch_kernel(const float* __restrict__ x,
                   const float* __restrict__ qb, const float* __restrict__ kb,
                   const float* __restrict__ vb, const float* __restrict__ pb,
                   const float* __restrict__ ls, float* __restrict__ out)
{
    extern __shared__ float sm[];
    float* qs  = sm;
    float* kss = sm + NTOK * QS;
    float* vsm = sm + 2 * NTOK * QS;
    const uint32_t* qsu = (const uint32_t*)qs;
    uint32_t* qsw = (uint32_t*)qs;
    uint32_t* vsw = (uint32_t*)vsm;

    const int bid  = blockIdx.x;
    const int win  = bid >> 1;              // window 0..2047
    const int s    = bid & 1;               // branch 0/1 (heads s*4..s*4+3)
    const int tid  = threadIdx.x;
    const int warp = tid >> 5;
    const int lane = tid & 31;
    const int r0   = (warp & 3) * 16;       // GEMM warp row tile (4 row groups)
    const int n0   = (warp >> 2) * 64;      // GEMM warp col tile (2 col groups)
    const int qr   = lane >> 2;             // quad row 0..7
    const int ql   = lane & 3;              // quad col 0..3
    const int ldrow = tid >> 5;             // staging row base 0..7
    const int ldcol = (tid & 31) * 4;       // staging col 0..124

    const uint32_t vsm_u = (uint32_t)__cvta_generic_to_shared(vsm);
    const uint32_t kss_u = (uint32_t)__cvta_generic_to_shared(kss);

    uint32_t af[8][4];

    // prefetch Q weights half 0 into kss strip
    ISSUE(WSRC(0, 0), kss_u);

    // load x branch slice [64][128] into qs (fp32)
    const float* xg = x + (size_t)win * (NTOK * CDIM);
    for (int t = tid; t < 64 * 32; t += THREADS) {
        int i = t >> 5, c4 = t & 31;
        *(float4*)&qs[i * QS + c4 * 4] = ((const float4*)xg)[i * 64 + s * 32 + c4];
    }
    __syncthreads();

    // =========== Phase 1: Q, K, V residual linears (per-GEMM epilogues) ===========
    float accQ[8][4];
    ZERO_ACC(accQ);
    {
        // --- Q GEMM (result held in regs until after V; epilogue last) ---
        LOAD_AF_F32(0);
        WAITSYNC(); ISSUE(WSRC(0, 1), vsm_u);
        MMA_LOOP(kss, accQ);
        LOAD_AF_F32(64);
        WAITSYNC(); ISSUE(WSRC(1, 0), kss_u);
        MMA_LOOP(vsm, accQ);

        // --- K GEMM ---
        float accK[8][4];
        ZERO_ACC(accK);
        LOAD_AF_F32(0);
        WAITSYNC(); ISSUE(WSRC(1, 1), vsm_u);
        MMA_LOOP(kss, accK);
        LOAD_AF_F32(64);
        WAITSYNC();
        MMA_LOOP(vsm, accK);
        __syncthreads();               // all reads of vsm stage done
        ISSUE(WSRC(2, 0), vsm_u);      // V-h0 -> vsm (kss now reserved for k data)

        // k epilogue: k = x + x*Kw + kb  (fp32; normalized in phase 2)
        {
            const int rr = r0 + qr;
#pragma unroll
            for (int nt = 0; nt < 8; ++nt) {
                const int c = n0 + nt * 8 + 2 * ql;
                float2 x0 = *(const float2*)&qs[rr * QS + c];
                float2 x1 = *(const float2*)&qs[(rr + 8) * QS + c];
                float2 kb2 = *(const float2*)&kb[s * 128 + c];
                *(float2*)&kss[rr * QS + c] =
                    make_float2(x0.x + accK[nt][0] + kb2.x, x0.y + accK[nt][1] + kb2.y);
                *(float2*)&kss[(rr + 8) * QS + c] =
                    make_float2(x1.x + accK[nt][2] + kb2.x, x1.y + accK[nt][3] + kb2.y);
            }
        }
    }
    {
        // --- V GEMM (single-buffered in vsm) ---
        float accV[8][4];
        ZERO_ACC(accV);
        LOAD_AF_F32(0);
        WAITSYNC();
        MMA_LOOP(vsm, accV);
        __syncthreads();
        ISSUE(WSRC(2, 1), vsm_u);
        LOAD_AF_F32(64);
        WAITSYNC();
        MMA_LOOP(vsm, accV);
        __syncthreads();               // vsm stage reads + ALL x reads complete

        // v epilogue (tf32 bits), then q epilogue (own-position RMW on qs)
        {
            const int rr = r0 + qr;
#pragma unroll
            for (int nt = 0; nt < 8; ++nt) {
                const int c = n0 + nt * 8 + 2 * ql;
                float2 x0 = *(const float2*)&qs[rr * QS + c];
                float2 x1 = *(const float2*)&qs[(rr + 8) * QS + c];
                float2 vb2 = *(const float2*)&vb[s * 128 + c];
                float2 qb2 = *(const float2*)&qb[s * 128 + c];
                *(uint2*)&vsw[rr * QS + c] =
                    make_uint2(f2tf(x0.x + accV[nt][0] + vb2.x), f2tf(x0.y + accV[nt][1] + vb2.y));
                *(uint2*)&vsw[(rr + 8) * QS + c] =
                    make_uint2(f2tf(x1.x + accV[nt][2] + vb2.x), f2tf(x1.y + accV[nt][3] + vb2.y));
                *(float2*)&qs[rr * QS + c] =
                    make_float2(x0.x + accQ[nt][0] + qb2.x, x0.y + accQ[nt][1] + qb2.y);
                *(float2*)&qs[(rr + 8) * QS + c] =
                    make_float2(x1.x + accQ[nt][2] + qb2.x, x1.y + accQ[nt][3] + qb2.y);
            }
        }
    }
    __syncthreads();

    // =========== Phase 2: l2-normalize q,k; fold logit scale; store tf32 bits ===========
#pragma unroll
    for (int t4 = 0; t4 < 2; ++t4) {
        int t = tid + t4 * THREADS;      // 512 tasks: {q,k} x 4 heads x 64 rows
        int bufsel = t >> 8;
        int h = (t >> 6) & 3;
        int i = t & 63;
        float* base = (bufsel ? kss : qs) + i * QS + h * HD;
        uint32_t* baseu = (uint32_t*)base;
        float4 vv[8];
        float ssq = 0.f;
#pragma unroll
        for (int u = 0; u < 8; ++u) {
            vv[u] = ((float4*)base)[u];
            ssq = fmaf(vv[u].x, vv[u].x, ssq);
            ssq = fmaf(vv[u].y, vv[u].y, ssq);
            ssq = fmaf(vv[u].z, vv[u].z, ssq);
            ssq = fmaf(vv[u].w, vv[u].w, ssq);
        }
        float inv = 1.f / fmaxf(sqrtf(ssq), 1e-12f);
        if (bufsel == 0) inv *= fminf(expf(ls[s * 4 + h]), 100.f);
#pragma unroll
        for (int u = 0; u < 8; ++u) {
            uint4 st;
            st.x = f2tf(vv[u].x * inv); st.y = f2tf(vv[u].y * inv);
            st.z = f2tf(vv[u].z * inv); st.w = f2tf(vv[u].w * inv);
            ((uint4*)baseu)[u] = st;
        }
    }
    __syncthreads();

    // =========== Phase 3: attention via tf32 mma, two warps per head ===========
    {
        const int h = warp >> 1;                 // local head 0..3
        const int mtb = (warp & 1) * 2;          // this warp's 2 row tiles
        const float* Tw = d_Tcomb +
            (size_t)((((win & (NWIN - 1)) * NHEADS + s * 4 + h)) << 12);
        const int s0l = (lane & ~3) | (ql >> 1);
        const bool odd = ql & 1;

#pragma unroll 1
        for (int mm = 0; mm < 2; ++mm) {
            const int i0r = (mtb + mm) * 16 + qr;

            uint32_t qa[4][4];
#pragma unroll
            for (int kt = 0; kt < 4; ++kt) {
                const uint32_t* ap = qsu + i0r * QS + h * HD + kt * 8 + ql;
                qa[kt][0] = ap[0];
                qa[kt][1] = ap[8 * QS];
                qa[kt][2] = ap[4];
                qa[kt][3] = ap[8 * QS + 4];
            }

            float S[8][4];
#pragma unroll
            for (int nt = 0; nt < 8; ++nt) { S[nt][0] = S[nt][1] = S[nt][2] = S[nt][3] = 0.f; }
#pragma unroll
            for (int kt = 0; kt < 4; ++kt) {
#pragma unroll
                for (int nt = 0; nt < 8; ++nt) {
                    const uint32_t* kp = (const uint32_t*)kss + (nt * 8 + qr) * QS + h * HD + kt * 8 + ql;
                    mma_tf32(S[nt][0], S[nt][1], S[nt][2], S[nt][3],
                             qa[kt][0], qa[kt][1], qa[kt][2], qa[kt][3], kp[0], kp[4]);
                }
            }

            float rmax0 = -1e30f, rmax1 = -1e30f;
#pragma unroll
            for (int nt = 0; nt < 8; ++nt) {
                float2 t0 = *(const float2*)&Tw[i0r * 64 + nt * 8 + 2 * ql];
                float2 t1 = *(const float2*)&Tw[(i0r + 8) * 64 + nt * 8 + 2 * ql];
                S[nt][0] += t0.x; S[nt][1] += t0.y;
                S[nt][2] += t1.x; S[nt][3] += t1.y;
                rmax0 = fmaxf(rmax0, fmaxf(S[nt][0], S[nt][1]));
                rmax1 = fmaxf(rmax1, fmaxf(S[nt][2], S[nt][3]));
            }
            rmax0 = fmaxf(rmax0, __shfl_xor_sync(0xffffffffu, rmax0, 1));
            rmax0 = fmaxf(rmax0, __shfl_xor_sync(0xffffffffu, rmax0, 2));
            rmax1 = fmaxf(rmax1, __shfl_xor_sync(0xffffffffu, rmax1, 1));
            rmax1 = fmaxf(rmax1, __shfl_xor_sync(0xffffffffu, rmax1, 2));

            float sum0 = 0.f, sum1 = 0.f;
#pragma unroll
            for (int nt = 0; nt < 8; ++nt) {
                S[nt][0] = __expf(S[nt][0] - rmax0); sum0 += S[nt][0];
                S[nt][1] = __expf(S[nt][1] - rmax0); sum0 += S[nt][1];
                S[nt][2] = __expf(S[nt][2] - rmax1); sum1 += S[nt][2];
                S[nt][3] = __expf(S[nt][3] - rmax1); sum1 += S[nt][3];
            }
            sum0 += __shfl_xor_sync(0xffffffffu, sum0, 1);
            sum0 += __shfl_xor_sync(0xffffffffu, sum0, 2);
            sum1 += __shfl_xor_sync(0xffffffffu, sum1, 1);
            sum1 += __shfl_xor_sync(0xffffffffu, sum1, 2);
            float inv0 = 1.f / sum0, inv1 = 1.f / sum1;

            uint32_t pa[8][4];
#pragma unroll
            for (int nt = 0; nt < 8; ++nt) {
                uint32_t u0 = f2tf(S[nt][0]), u1 = f2tf(S[nt][1]);
                uint32_t u2 = f2tf(S[nt][2]), u3 = f2tf(S[nt][3]);
                uint32_t v0 = __shfl_sync(0xffffffffu, u0, s0l);
                uint32_t v1 = __shfl_sync(0xffffffffu, u1, s0l);
                pa[nt][0] = odd ? v1 : v0;
                uint32_t v2 = __shfl_sync(0xffffffffu, u2, s0l);
                uint32_t v3 = __shfl_sync(0xffffffffu, u3, s0l);
                pa[nt][1] = odd ? v3 : v2;
                v0 = __shfl_sync(0xffffffffu, u0, s0l + 2);
                v1 = __shfl_sync(0xffffffffu, u1, s0l + 2);
                pa[nt][2] = odd ? v1 : v0;
                v2 = __shfl_sync(0xffffffffu, u2, s0l + 2);
                v3 = __shfl_sync(0xffffffffu, u3, s0l + 2);
                pa[nt][3] = odd ? v3 : v2;
            }

            float O[4][4];
#pragma unroll
            for (int nd = 0; nd < 4; ++nd) { O[nd][0] = O[nd][1] = O[nd][2] = O[nd][3] = 0.f; }
#pragma unroll
            for (int kt = 0; kt < 8; ++kt) {
#pragma unroll
                for (int nd = 0; nd < 4; ++nd) {
                    const uint32_t* vp = (const uint32_t*)vsm + (kt * 8 + ql) * QS + h * HD + nd * 8 + qr;
                    mma_tf32(O[nd][0], O[nd][1], O[nd][2], O[nd][3],
                             pa[kt][0], pa[kt][1], pa[kt][2], pa[kt][3], vp[0], vp[4 * QS]);
                }
            }

#pragma unroll
            for (int nd = 0; nd < 4; ++nd) {
                uint2 st0, st1;
                st0.x = f2tf(O[nd][0] * inv0); st0.y = f2tf(O[nd][1] * inv0);
                st1.x = f2tf(O[nd][2] * inv1); st1.y = f2tf(O[nd][3] * inv1);
                *(uint2*)&qsw[i0r * QS + h * HD + nd * 8 + 2 * ql] = st0;
                *(uint2*)&qsw[(i0r + 8) * QS + h * HD + nd * 8 + 2 * ql] = st1;
            }
        }
    }
    __syncthreads();   // O (tf32 bits) in qs; kss/vsm now dead

    // =========== Phase 4: output projection, store to gmem ===========
    float* og = out + (size_t)win * (NTOK * CDIM);
    {
        float accP[8][4];
        ZERO_ACC(accP);
        ISSUE(WSRC(3, 0), kss_u);
        LOAD_AF_BITS(0);
        WAITSYNC(); ISSUE(WSRC(3, 1), vsm_u);
        MMA_LOOP(kss, accP);
        LOAD_AF_BITS(64);
        WAITSYNC();
        MMA_LOOP(vsm, accP);

        const int rr = r0 + qr;
#pragma unroll
        for (int nt = 0; nt < 8; ++nt) {
            const int c = n0 + nt * 8 + 2 * ql;
            float2 pb2 = *(const float2*)&pb[s * 128 + c];
            *(float2*)&og[rr * CDIM + s * 128 + c] =
                make_float2(accP[nt][0] + pb2.x, accP[nt][1] + pb2.y);
            *(float2*)&og[(rr + 8) * CDIM + s * 128 + c] =
                make_float2(accP[nt][2] + pb2.x, accP[nt][3] + pb2.y);
        }
    }
}

extern "C" void kernel_launch(void* const* d_in, const int* in_sizes, int n_in,
                              void* d_out, int out_size) {
    const float* x    = (const float*)d_in[0];
    const float* mask = (const float*)d_in[1];
    const float* qw   = (const float*)d_in[2];
    const float* qb   = (const float*)d_in[3];
    const float* kw   = (const float*)d_in[4];
    const float* kb   = (const float*)d_in[5];
    const float* vw   = (const float*)d_in[6];
    const float* vb   = (const float*)d_in[7];
    const float* pw   = (const float*)d_in[8];
    const float* pb   = (const float*)d_in[9];
    const float* w1   = (const float*)d_in[10];
    const float* b1   = (const float*)d_in[11];
    const float* w2   = (const float*)d_in[12];
    const float* ls   = (const float*)d_in[13];
    const float* rpb  = (const float*)d_in[14];
    const int*   rpi  = (const int*)d_in[15];
    float* out = (float*)d_out;

    static bool inited = false;
    if (!inited) {
        cudaFuncSetAttribute(swin_branch_kernel,
                             cudaFuncAttributeMaxDynamicSharedMemorySize, SMEM_BYTES);
        inited = true;
    }

    wconv_kernel<<<512, 256>>>(qw, kw, vw, pw);
    cpb_mlp_kernel<<<225, 128>>>(rpb, w1, b1, w2);
    bias_combine_kernel<<<(NWIN * NHEADS * NTOK * NTOK + 255) / 256, 256>>>(rpi, mask);
    swin_branch_kernel<<<NBATCH * 2, THREADS, SMEM_BYTES>>>(x, qb, kb, vb, pb, ls, out);
}

// round 11
// speedup vs baseline: 1.7731x; 1.2103x over previous
#include <cuda_runtime.h>
#include <math.h>
#include <stdint.h>

#define NTOK 64
#define CDIM 256
#define NHEADS 8
#define HD   32
#define QSA  132          // qs stride: 4 mod 32 -> conflict-free qr-row (A-side) access
#define QSW  136          // kss/vsm stride: 8 mod 32 -> conflict-free ql-row (B-side) access
#define NWIN 64
#define NBATCH 2048
#define THREADS 256

#define SMEM_FLOATS (NTOK * (QSA + 2 * QSW))
#define SMEM_BYTES  (SMEM_FLOATS * 4)     // 103424 B -> 2 CTAs/SM

__device__ float d_tbl2[225 * NHEADS];
__device__ float d_Tcomb[NWIN * NHEADS * NTOK * NTOK];   // 16*sigmoid(bias)+mask, 8MB
__device__ uint32_t d_wtf[4 * 32768];                    // q,k,v,p weights as tf32 bits

// ---------------- prologue 0: weights -> tf32 bits ----------------
__device__ __forceinline__ uint32_t f2tf(float f) {
    uint32_t u; asm("cvt.rna.tf32.f32 %0, %1;" : "=r"(u) : "f"(f)); return u;
}

__global__ void wconv_kernel(const float* __restrict__ qw, const float* __restrict__ kw,
                             const float* __restrict__ vw, const float* __restrict__ pw) {
    int idx = blockIdx.x * blockDim.x + threadIdx.x;
    if (idx >= 4 * 32768) return;
    int sel = idx >> 15, off = idx & 32767;
    float v = (sel == 0) ? qw[off] : (sel == 1) ? kw[off] : (sel == 2) ? vw[off] : pw[off];
    d_wtf[idx] = f2tf(v);
}

// ---------------- prologue 1: rpb_table -> MLP -> (225, 8) ----------------
__global__ void cpb_mlp_kernel(const float* __restrict__ rpb,
                               const float* __restrict__ w1,
                               const float* __restrict__ b1,
                               const float* __restrict__ w2) {
    __shared__ float acc[NHEADS];
    int p = blockIdx.x;          // 0..224
    int j = threadIdx.x;         // 0..127
    if (j < NHEADS) acc[j] = 0.f;
    __syncthreads();
    float t0 = rpb[p * 2 + 0];
    float t1 = rpb[p * 2 + 1];
    float hid = fmaxf(t0 * w1[j] + t1 * w1[128 + j] + b1[j], 0.f);
#pragma unroll
    for (int h = 0; h < NHEADS; ++h) {
        float pv = hid * w2[j * 8 + h];
#pragma unroll
        for (int o = 16; o; o >>= 1) pv += __shfl_xor_sync(0xffffffffu, pv, o);
        if ((j & 31) == 0) atomicAdd(&acc[h], pv);
    }
    __syncthreads();
    if (j < NHEADS) d_tbl2[p * 8 + j] = acc[j];
}

// ---------------- prologue 2: combined bias+mask table ----------------
__global__ void bias_combine_kernel(const int* __restrict__ rpi,
                                    const float* __restrict__ mask) {
    int idx = blockIdx.x * blockDim.x + threadIdx.x;
    if (idx >= NWIN * NHEADS * NTOK * NTOK) return;
    int ij = idx & 4095;
    int h  = (idx >> 12) & 7;
    int w  = idx >> 15;
    float bv = d_tbl2[rpi[ij] * 8 + h];
    d_Tcomb[idx] = 16.f / (1.f + expf(-bv)) + mask[w * 4096 + ij];
}

// ---------------- mma helper ----------------
__device__ __forceinline__ void mma_tf32(float& d0, float& d1, float& d2, float& d3,
                                         uint32_t a0, uint32_t a1, uint32_t a2, uint32_t a3,
                                         uint32_t b0, uint32_t b1) {
    asm volatile(
        "mma.sync.aligned.m16n8k8.row.col.f32.tf32.tf32.f32 "
        "{%0,%1,%2,%3},{%4,%5,%6,%7},{%8,%9},{%0,%1,%2,%3};"
        : "+f"(d0), "+f"(d1), "+f"(d2), "+f"(d3)
        : "r"(a0), "r"(a1), "r"(a2), "r"(a3), "r"(b0), "r"(b1));
}

// weight source in d_wtf: w 0..3 = q,k,v,p ; per-branch half [64][128]
#define WSRC(w, hf) (d_wtf + (w) * 32768 + s * 16384 + (hf) * 8192)

// issue the 8 cp.async for one [64][128] weight stage + commit (stride QSW)
#define ISSUE(SRC, DSTU) do {                                                \
    const uint32_t* _s0 = (SRC) + ldrow * 128 + ldcol;                       \
    uint32_t _d0 = (DSTU) + (uint32_t)((ldrow * QSW + ldcol) * 4);           \
    _Pragma("unroll")                                                        \
    for (int k_ = 0; k_ < 8; ++k_)                                           \
        asm volatile("cp.async.cg.shared.global [%0], [%1], 16;\n"           \
            :: "r"(_d0 + (uint32_t)(k_ * 8 * QSW * 4)),                      \
               "l"(_s0 + k_ * 8 * 128) : "memory");                          \
    asm volatile("cp.async.commit_group;\n" ::: "memory");                   \
} while (0)

#define WAITSYNC() do {                                                      \
    asm volatile("cp.async.wait_group 0;\n" ::: "memory");                   \
    __syncthreads();                                                         \
} while (0)

// 16x64 warp-tile mma over one staged [64 K][128 N] weight tile (stride QSW)
#define MMA_LOOP(BUFP, ACC) do {                                             \
    const uint32_t* _bu = (const uint32_t*)(BUFP);                           \
    _Pragma("unroll")                                                        \
    for (int kt = 0; kt < 8; ++kt) {                                         \
        const uint32_t* bp = _bu + (kt * 8 + ql) * QSW + n0 + qr;            \
        _Pragma("unroll")                                                    \
        for (int nt = 0; nt < 8; ++nt) {                                     \
            mma_tf32(ACC[nt][0], ACC[nt][1], ACC[nt][2], ACC[nt][3],         \
                     af[kt][0], af[kt][1], af[kt][2], af[kt][3],             \
                     bp[nt * 8], bp[4 * QSW + nt * 8]);                      \
        }                                                                    \
    }                                                                        \
} while (0)

#define LOAD_AF_F32(CB) do {                                                 \
    _Pragma("unroll")                                                        \
    for (int kt = 0; kt < 8; ++kt) {                                         \
        const float* ap = qs + (r0 + qr) * QSA + (CB) + kt * 8 + ql;         \
        af[kt][0] = f2tf(ap[0]);                                             \
        af[kt][1] = f2tf(ap[8 * QSA]);                                       \
        af[kt][2] = f2tf(ap[4]);                                             \
        af[kt][3] = f2tf(ap[8 * QSA + 4]);                                   \
    }                                                                        \
} while (0)

#define LOAD_AF_BITS(CB) do {                                                \
    _Pragma("unroll")                                                        \
    for (int kt = 0; kt < 8; ++kt) {                                         \
        const uint32_t* ap = qsu + (r0 + qr) * QSA + (CB) + kt * 8 + ql;     \
        af[kt][0] = ap[0];                                                   \
        af[kt][1] = ap[8 * QSA];                                             \
        af[kt][2] = ap[4];                                                   \
        af[kt][3] = ap[8 * QSA + 4];                                         \
    }                                                                        \
} while (0)

#define ZERO_ACC(A) do {                                                     \
    _Pragma("unroll")                                                        \
    for (int nt = 0; nt < 8; ++nt)                                           \
        { A[nt][0] = 0.f; A[nt][1] = 0.f; A[nt][2] = 0.f; A[nt][3] = 0.f; }  \
} while (0)

// ---------------- main fused kernel: one CTA per (window, branch) ----------------
__global__ void __launch_bounds__(THREADS, 2)
swin_branch_kernel(const float* __restrict__ x,
                   const float* __restrict__ qb, const float* __restrict__ kb,
                   const float* __restrict__ vb, const float* __restrict__ pb,
                   const float* __restrict__ ls, float* __restrict__ out)
{
    extern __shared__ float sm[];
    float* qs  = sm;                              // 64 x 132
    float* kss = sm + NTOK * QSA;                 // 64 x 136
    float* vsm = sm + NTOK * (QSA + QSW);         // 64 x 136
    const uint32_t* qsu = (const uint32_t*)qs;
    uint32_t* qsw = (uint32_t*)qs;
    uint32_t* vsw = (uint32_t*)vsm;

    const int bid  = blockIdx.x;
    const int win  = bid >> 1;              // window 0..2047
    const int s    = bid & 1;               // branch 0/1 (heads s*4..s*4+3)
    const int tid  = threadIdx.x;
    const int warp = tid >> 5;
    const int lane = tid & 31;
    const int r0   = (warp & 3) * 16;       // GEMM warp row tile (4 row groups)
    const int n0   = (warp >> 2) * 64;      // GEMM warp col tile (2 col groups)
    const int qr   = lane >> 2;             // quad row 0..7
    const int ql   = lane & 3;              // quad col 0..3
    const int ldrow = tid >> 5;             // staging row base 0..7
    const int ldcol = (tid & 31) * 4;       // staging col 0..124

    const uint32_t vsm_u = (uint32_t)__cvta_generic_to_shared(vsm);
    const uint32_t kss_u = (uint32_t)__cvta_generic_to_shared(kss);

    uint32_t af[8][4];

    // prefetch Q weights half 0 into kss strip
    ISSUE(WSRC(0, 0), kss_u);

    // load x branch slice [64][128] into qs (fp32)
    const float* xg = x + (size_t)win * (NTOK * CDIM);
    for (int t = tid; t < 64 * 32; t += THREADS) {
        int i = t >> 5, c4 = t & 31;
        *(float4*)&qs[i * QSA + c4 * 4] = ((const float4*)xg)[i * 64 + s * 32 + c4];
    }
    __syncthreads();

    // =========== Phase 1: Q, K, V residual linears (per-GEMM epilogues) ===========
    float accQ[8][4];
    ZERO_ACC(accQ);
    {
        // --- Q GEMM (result held in regs until after V; epilogue last) ---
        LOAD_AF_F32(0);
        WAITSYNC(); ISSUE(WSRC(0, 1), vsm_u);
        MMA_LOOP(kss, accQ);
        LOAD_AF_F32(64);
        WAITSYNC(); ISSUE(WSRC(1, 0), kss_u);
        MMA_LOOP(vsm, accQ);

        // --- K GEMM ---
        float accK[8][4];
        ZERO_ACC(accK);
        LOAD_AF_F32(0);
        WAITSYNC(); ISSUE(WSRC(1, 1), vsm_u);
        MMA_LOOP(kss, accK);
        LOAD_AF_F32(64);
        WAITSYNC();
        MMA_LOOP(vsm, accK);
        __syncthreads();               // all reads of vsm stage done
        ISSUE(WSRC(2, 0), vsm_u);      // V-h0 -> vsm (kss now reserved for k data)

        // k epilogue: k = x + x*Kw + kb  (fp32; normalized in phase 2)
        {
            const int rr = r0 + qr;
#pragma unroll
            for (int nt = 0; nt < 8; ++nt) {
                const int c = n0 + nt * 8 + 2 * ql;
                float2 x0 = *(const float2*)&qs[rr * QSA + c];
                float2 x1 = *(const float2*)&qs[(rr + 8) * QSA + c];
                float2 kb2 = *(const float2*)&kb[s * 128 + c];
                *(float2*)&kss[rr * QSW + c] =
                    make_float2(x0.x + accK[nt][0] + kb2.x, x0.y + accK[nt][1] + kb2.y);
                *(float2*)&kss[(rr + 8) * QSW + c] =
                    make_float2(x1.x + accK[nt][2] + kb2.x, x1.y + accK[nt][3] + kb2.y);
            }
        }
    }
    {
        // --- V GEMM (single-buffered in vsm) ---
        float accV[8][4];
        ZERO_ACC(accV);
        LOAD_AF_F32(0);
        WAITSYNC();
        MMA_LOOP(vsm, accV);
        __syncthreads();
        ISSUE(WSRC(2, 1), vsm_u);
        LOAD_AF_F32(64);
        WAITSYNC();
        MMA_LOOP(vsm, accV);
        __syncthreads();               // vsm stage reads + ALL x reads complete

        // v epilogue (tf32 bits), then q epilogue (own-position RMW on qs)
        {
            const int rr = r0 + qr;
#pragma unroll
            for (int nt = 0; nt < 8; ++nt) {
                const int c = n0 + nt * 8 + 2 * ql;
                float2 x0 = *(const float2*)&qs[rr * QSA + c];
                float2 x1 = *(const float2*)&qs[(rr + 8) * QSA + c];
                float2 vb2 = *(const float2*)&vb[s * 128 + c];
                float2 qb2 = *(const float2*)&qb[s * 128 + c];
                *(uint2*)&vsw[rr * QSW + c] =
                    make_uint2(f2tf(x0.x + accV[nt][0] + vb2.x), f2tf(x0.y + accV[nt][1] + vb2.y));
                *(uint2*)&vsw[(rr + 8) * QSW + c] =
                    make_uint2(f2tf(x1.x + accV[nt][2] + vb2.x), f2tf(x1.y + accV[nt][3] + vb2.y));
                *(float2*)&qs[rr * QSA + c] =
                    make_float2(x0.x + accQ[nt][0] + qb2.x, x0.y + accQ[nt][1] + qb2.y);
                *(float2*)&qs[(rr + 8) * QSA + c] =
                    make_float2(x1.x + accQ[nt][2] + qb2.x, x1.y + accQ[nt][3] + qb2.y);
            }
        }
    }
    __syncthreads();

    // =========== Phase 2: l2-normalize q,k; fold logit scale; store tf32 bits ===========
#pragma unroll
    for (int t4 = 0; t4 < 2; ++t4) {
        int t = tid + t4 * THREADS;      // 512 tasks: {q,k} x 4 heads x 64 rows
        int bufsel = t >> 8;
        int h = (t >> 6) & 3;
        int i = t & 63;
        float* base = bufsel ? (kss + i * QSW + h * HD) : (qs + i * QSA + h * HD);
        uint32_t* baseu = (uint32_t*)base;
        float4 vv[8];
        float ssq = 0.f;
#pragma unroll
        for (int u = 0; u < 8; ++u) {
            vv[u] = ((float4*)base)[u];
            ssq = fmaf(vv[u].x, vv[u].x, ssq);
            ssq = fmaf(vv[u].y, vv[u].y, ssq);
            ssq = fmaf(vv[u].z, vv[u].z, ssq);
            ssq = fmaf(vv[u].w, vv[u].w, ssq);
        }
        float inv = 1.f / fmaxf(sqrtf(ssq), 1e-12f);
        if (bufsel == 0) inv *= fminf(expf(ls[s * 4 + h]), 100.f);
#pragma unroll
        for (int u = 0; u < 8; ++u) {
            uint4 st;
            st.x = f2tf(vv[u].x * inv); st.y = f2tf(vv[u].y * inv);
            st.z = f2tf(vv[u].z * inv); st.w = f2tf(vv[u].w * inv);
            ((uint4*)baseu)[u] = st;
        }
    }
    __syncthreads();

    // =========== Phase 3: attention via tf32 mma, two warps per head ===========
    {
        const int h = warp >> 1;                 // local head 0..3
        const int mtb = (warp & 1) * 2;          // this warp's 2 row tiles
        const float* Tw = d_Tcomb +
            (size_t)((((win & (NWIN - 1)) * NHEADS + s * 4 + h)) << 12);
        const int s0l = (lane & ~3) | (ql >> 1);
        const bool odd = ql & 1;

#pragma unroll 1
        for (int mm = 0; mm < 2; ++mm) {
            const int i0r = (mtb + mm) * 16 + qr;

            uint32_t qa[4][4];
#pragma unroll
            for (int kt = 0; kt < 4; ++kt) {
                const uint32_t* ap = qsu + i0r * QSA + h * HD + kt * 8 + ql;
                qa[kt][0] = ap[0];
                qa[kt][1] = ap[8 * QSA];
                qa[kt][2] = ap[4];
                qa[kt][3] = ap[8 * QSA + 4];
            }

            float S[8][4];
#pragma unroll
            for (int nt = 0; nt < 8; ++nt) { S[nt][0] = S[nt][1] = S[nt][2] = S[nt][3] = 0.f; }
#pragma unroll
            for (int kt = 0; kt < 4; ++kt) {
#pragma unroll
                for (int nt = 0; nt < 8; ++nt) {
                    const uint32_t* kp = (const uint32_t*)kss + (nt * 8 + qr) * QSW + h * HD + kt * 8 + ql;
                    mma_tf32(S[nt][0], S[nt][1], S[nt][2], S[nt][3],
                             qa[kt][0], qa[kt][1], qa[kt][2], qa[kt][3], kp[0], kp[4]);
                }
            }

            float rmax0 = -1e30f, rmax1 = -1e30f;
#pragma unroll
            for (int nt = 0; nt < 8; ++nt) {
                float2 t0 = *(const float2*)&Tw[i0r * 64 + nt * 8 + 2 * ql];
                float2 t1 = *(const float2*)&Tw[(i0r + 8) * 64 + nt * 8 + 2 * ql];
                S[nt][0] += t0.x; S[nt][1] += t0.y;
                S[nt][2] += t1.x; S[nt][3] += t1.y;
                rmax0 = fmaxf(rmax0, fmaxf(S[nt][0], S[nt][1]));
                rmax1 = fmaxf(rmax1, fmaxf(S[nt][2], S[nt][3]));
            }
            rmax0 = fmaxf(rmax0, __shfl_xor_sync(0xffffffffu, rmax0, 1));
            rmax0 = fmaxf(rmax0, __shfl_xor_sync(0xffffffffu, rmax0, 2));
            rmax1 = fmaxf(rmax1, __shfl_xor_sync(0xffffffffu, rmax1, 1));
            rmax1 = fmaxf(rmax1, __shfl_xor_sync(0xffffffffu, rmax1, 2));

            float sum0 = 0.f, sum1 = 0.f;
#pragma unroll
            for (int nt = 0; nt < 8; ++nt) {
                S[nt][0] = __expf(S[nt][0] - rmax0); sum0 += S[nt][0];
                S[nt][1] = __expf(S[nt][1] - rmax0); sum0 += S[nt][1];
                S[nt][2] = __expf(S[nt][2] - rmax1); sum1 += S[nt][2];
                S[nt][3] = __expf(S[nt][3] - rmax1); sum1 += S[nt][3];
            }
            sum0 += __shfl_xor_sync(0xffffffffu, sum0, 1);
            sum0 += __shfl_xor_sync(0xffffffffu, sum0, 2);
            sum1 += __shfl_xor_sync(0xffffffffu, sum1, 1);
            sum1 += __shfl_xor_sync(0xffffffffu, sum1, 2);
            float inv0 = 1.f / sum0, inv1 = 1.f / sum1;

            uint32_t pa[8][4];
#pragma unroll
            for (int nt = 0; nt < 8; ++nt) {
                uint32_t u0 = f2tf(S[nt][0]), u1 = f2tf(S[nt][1]);
                uint32_t u2 = f2tf(S[nt][2]), u3 = f2tf(S[nt][3]);
                uint32_t v0 = __shfl_sync(0xffffffffu, u0, s0l);
                uint32_t v1 = __shfl_sync(0xffffffffu, u1, s0l);
                pa[nt][0] = odd ? v1 : v0;
                uint32_t v2 = __shfl_sync(0xffffffffu, u2, s0l);
                uint32_t v3 = __shfl_sync(0xffffffffu, u3, s0l);
                pa[nt][1] = odd ? v3 : v2;
                v0 = __shfl_sync(0xffffffffu, u0, s0l + 2);
                v1 = __shfl_sync(0xffffffffu, u1, s0l + 2);
                pa[nt][2] = odd ? v1 : v0;
                v2 = __shfl_sync(0xffffffffu, u2, s0l + 2);
                v3 = __shfl_sync(0xffffffffu, u3, s0l + 2);
                pa[nt][3] = odd ? v3 : v2;
            }

            float O[4][4];
#pragma unroll
            for (int nd = 0; nd < 4; ++nd) { O[nd][0] = O[nd][1] = O[nd][2] = O[nd][3] = 0.f; }
#pragma unroll
            for (int kt = 0; kt < 8; ++kt) {
#pragma unroll
                for (int nd = 0; nd < 4; ++nd) {
                    const uint32_t* vp = (const uint32_t*)vsm + (kt * 8 + ql) * QSW + h * HD + nd * 8 + qr;
                    mma_tf32(O[nd][0], O[nd][1], O[nd][2], O[nd][3],
                             pa[kt][0], pa[kt][1], pa[kt][2], pa[kt][3], vp[0], vp[4 * QSW]);
                }
            }

#pragma unroll
            for (int nd = 0; nd < 4; ++nd) {
                uint2 st0, st1;
                st0.x = f2tf(O[nd][0] * inv0); st0.y = f2tf(O[nd][1] * inv0);
                st1.x = f2tf(O[nd][2] * inv1); st1.y = f2tf(O[nd][3] * inv1);
                *(uint2*)&qsw[i0r * QSA + h * HD + nd * 8 + 2 * ql] = st0;
                *(uint2*)&qsw[(i0r + 8) * QSA + h * HD + nd * 8 + 2 * ql] = st1;
            }
        }
    }
    __syncthreads();   // O (tf32 bits) in qs; kss/vsm now dead

    // =========== Phase 4: output projection, store to gmem ===========
    float* og = out + (size_t)win * (NTOK * CDIM);
    {
        float accP[8][4];
        ZERO_ACC(accP);
        ISSUE(WSRC(3, 0), kss_u);
        LOAD_AF_BITS(0);
        WAITSYNC(); ISSUE(WSRC(3, 1), vsm_u);
        MMA_LOOP(kss, accP);
        LOAD_AF_BITS(64);
        WAITSYNC();
        MMA_LOOP(vsm, accP);

        const int rr = r0 + qr;
#pragma unroll
        for (int nt = 0; nt < 8; ++nt) {
            const int c = n0 + nt * 8 + 2 * ql;
            float2 pb2 = *(const float2*)&pb[s * 128 + c];
            *(float2*)&og[rr * CDIM + s * 128 + c] =
                make_float2(accP[nt][0] + pb2.x, accP[nt][1] + pb2.y);
            *(float2*)&og[(rr + 8) * CDIM + s * 128 + c] =
                make_float2(accP[nt][2] + pb2.x, accP[nt][3] + pb2.y);
        }
    }
}

extern "C" void kernel_launch(void* const* d_in, const int* in_sizes, int n_in,
                              void* d_out, int out_size) {
    const float* x    = (const float*)d_in[0];
    const float* mask = (const float*)d_in[1];
    const float* qw   = (const float*)d_in[2];
    const float* qb   = (const float*)d_in[3];
    const float* kw   = (const float*)d_in[4];
    const float* kb   = (const float*)d_in[5];
    const float* vw   = (const float*)d_in[6];
    const float* vb   = (const float*)d_in[7];
    const float* pw   = (const float*)d_in[8];
    const float* pb   = (const float*)d_in[9];
    const float* w1   = (const float*)d_in[10];
    const float* b1   = (const float*)d_in[11];
    const float* w2   = (const float*)d_in[12];
    const float* ls   = (const float*)d_in[13];
    const float* rpb  = (const float*)d_in[14];
    const int*   rpi  = (const int*)d_in[15];
    float* out = (float*)d_out;

    static bool inited = false;
    if (!inited) {
        cudaFuncSetAttribute(swin_branch_kernel,
                             cudaFuncAttributeMaxDynamicSharedMemorySize, SMEM_BYTES);
        inited = true;
    }

    wconv_kernel<<<512, 256>>>(qw, kw, vw, pw);
    cpb_mlp_kernel<<<225, 128>>>(rpb, w1, b1, w2);
    bias_combine_kernel<<<(NWIN * NHEADS * NTOK * NTOK + 255) / 256, 256>>>(rpi, mask);
    swin_branch_kernel<<<NBATCH * 2, THREADS, SMEM_BYTES>>>(x, qb, kb, vb, pb, ls, out);
}

// round 12
// speedup vs baseline: 2.9303x; 1.6527x over previous
#include <cuda_runtime.h>
#include <cuda_fp16.h>
#include <math.h>
#include <stdint.h>

#define NTOK 64
#define CDIM 256
#define NHEADS 8
#define HD   32
#define NWIN 64
#define NBATCH 2048
#define THREADS 256

// strides in uint32 (half2) units
#define S2Q 68            // qs: 4 mod 32 -> conflict-free qr-row access
#define S2K 72            // kbuf: 8 mod 32 -> conflict-free ql-row access
#define S2V 136           // vbuf: 8 mod 32
#define S2W 136           // weight stages: 8 mod 32

// smem layout (uint32 units)
#define OFF_Q  0                        // 64 x 68
#define OFF_K  (64 * S2Q)               // 64 x 72
#define OFF_V  (OFF_K + 64 * S2K)       // 32 x 136
#define OFF_WA (OFF_V + 32 * S2V)       // 32 x 136
#define OFF_WB (OFF_WA + 32 * S2W)      // 32 x 136
#define SMEM_U32 (OFF_WB + 32 * S2W)
#define SMEM_BYTES (SMEM_U32 * 4)       // 88064 B -> 2 CTAs/SM

__device__ float d_tbl2[225 * NHEADS];
__device__ float d_Tcomb[NWIN * NHEADS * NTOK * NTOK];   // 16*sigmoid(bias)+mask, 8MB
__device__ uint32_t d_wh[4 * 2 * 2 * 32 * 128];          // fp16 k-pair packed weights

// ---------------- helpers ----------------
__device__ __forceinline__ uint32_t pkh2(float a, float b) {
    __half2 h = __floats2half2_rn(a, b);
    return *reinterpret_cast<uint32_t*>(&h);
}
__device__ __forceinline__ float2 uph2(uint32_t u) {
    __half2 h = *reinterpret_cast<__half2*>(&u);
    return __half22float2(h);
}

// ---------------- prologue 0: weights -> fp16 k-pair pack ----------------
// d_wh[w][s][hf][kk 0..31][n 0..127]: half2{ W[s][hf*64+2kk][n], W[s][..+1][n] }
__global__ void whconv_kernel(const float* __restrict__ qw, const float* __restrict__ kw,
                              const float* __restrict__ vw, const float* __restrict__ pw) {
    int idx = blockIdx.x * blockDim.x + threadIdx.x;
    if (idx >= 4 * 2 * 2 * 32 * 128) return;
    int w  = idx >> 14;
    int s  = (idx >> 13) & 1;
    int hf = (idx >> 12) & 1;
    int kk = (idx >> 7) & 31;
    int n  = idx & 127;
    const float* src = (w == 0) ? qw : (w == 1) ? kw : (w == 2) ? vw : pw;
    int c = hf * 64 + 2 * kk;
    float v0 = src[s * 16384 + c * 128 + n];
    float v1 = src[s * 16384 + (c + 1) * 128 + n];
    d_wh[idx] = pkh2(v0, v1);
}

// ---------------- prologue 1: rpb_table -> MLP -> (225, 8) ----------------
__global__ void cpb_mlp_kernel(const float* __restrict__ rpb,
                               const float* __restrict__ w1,
                               const float* __restrict__ b1,
                               const float* __restrict__ w2) {
    __shared__ float acc[NHEADS];
    int p = blockIdx.x;
    int j = threadIdx.x;
    if (j < NHEADS) acc[j] = 0.f;
    __syncthreads();
    float t0 = rpb[p * 2 + 0];
    float t1 = rpb[p * 2 + 1];
    float hid = fmaxf(t0 * w1[j] + t1 * w1[128 + j] + b1[j], 0.f);
#pragma unroll
    for (int h = 0; h < NHEADS; ++h) {
        float pv = hid * w2[j * 8 + h];
#pragma unroll
        for (int o = 16; o; o >>= 1) pv += __shfl_xor_sync(0xffffffffu, pv, o);
        if ((j & 31) == 0) atomicAdd(&acc[h], pv);
    }
    __syncthreads();
    if (j < NHEADS) d_tbl2[p * 8 + j] = acc[j];
}

// ---------------- prologue 2: combined bias+mask table ----------------
__global__ void bias_combine_kernel(const int* __restrict__ rpi,
                                    const float* __restrict__ mask) {
    int idx = blockIdx.x * blockDim.x + threadIdx.x;
    if (idx >= NWIN * NHEADS * NTOK * NTOK) return;
    int ij = idx & 4095;
    int h  = (idx >> 12) & 7;
    int w  = idx >> 15;
    float bv = d_tbl2[rpi[ij] * 8 + h];
    d_Tcomb[idx] = 16.f / (1.f + expf(-bv)) + mask[w * 4096 + ij];
}

// ---------------- fp16 mma m16n8k16 ----------------
__device__ __forceinline__ void mma_f16(float& d0, float& d1, float& d2, float& d3,
                                        uint32_t a0, uint32_t a1, uint32_t a2, uint32_t a3,
                                        uint32_t b0, uint32_t b1) {
    asm volatile(
        "mma.sync.aligned.m16n8k16.row.col.f32.f16.f16.f32 "
        "{%0,%1,%2,%3},{%4,%5,%6,%7},{%8,%9},{%0,%1,%2,%3};"
        : "+f"(d0), "+f"(d1), "+f"(d2), "+f"(d3)
        : "r"(a0), "r"(a1), "r"(a2), "r"(a3), "r"(b0), "r"(b1));
}

// weight source: w 0..3 = q,k,v,p; half hf -> [32 kk][128 n] uint32 block
#define WSRC(w, hf) (d_wh + (((w) * 2 + s) * 2 + (hf)) * 4096)

// stage one [32 kk][128 n] uint32 weight half via 4 cp.async per thread
#define ISSUE(SRC, DSTU) do {                                                \
    const uint32_t* _s0 = (SRC) + ldrow * 128 + ldcol;                       \
    uint32_t _d0 = (DSTU) + (uint32_t)((ldrow * S2W + ldcol) * 4);           \
    _Pragma("unroll")                                                        \
    for (int k_ = 0; k_ < 4; ++k_)                                           \
        asm volatile("cp.async.cg.shared.global [%0], [%1], 16;\n"           \
            :: "r"(_d0 + (uint32_t)(k_ * 8 * S2W * 4)),                      \
               "l"(_s0 + k_ * 8 * 128) : "memory");                          \
    asm volatile("cp.async.commit_group;\n" ::: "memory");                   \
} while (0)

#define WAITSYNC() do {                                                      \
    asm volatile("cp.async.wait_group 0;\n" ::: "memory");                   \
    __syncthreads();                                                         \
} while (0)

// 16x64 warp-tile fp16 mma over one staged weight half (4 k16-tiles)
#define MMA_LOOP(BUFU, ACC) do {                                             \
    const uint32_t* _bu = (BUFU);                                            \
    _Pragma("unroll")                                                        \
    for (int kt = 0; kt < 4; ++kt) {                                         \
        const uint32_t* bp = _bu + (kt * 8 + ql) * S2W + n0 + qr;            \
        _Pragma("unroll")                                                    \
        for (int nt = 0; nt < 8; ++nt) {                                     \
            mma_f16(ACC[nt][0], ACC[nt][1], ACC[nt][2], ACC[nt][3],          \
                    af[kt][0], af[kt][1], af[kt][2], af[kt][3],              \
                    bp[nt * 8], bp[4 * S2W + nt * 8]);                       \
        }                                                                    \
    }                                                                        \
} while (0)

// A fragments (fp16 pairs) from qs, half hf (k cols 64*hf..64*hf+63)
#define LOAD_AF(HF) do {                                                     \
    _Pragma("unroll")                                                        \
    for (int kt = 0; kt < 4; ++kt) {                                         \
        const uint32_t* ap = qs2 + (r0 + qr) * S2Q + (HF) * 32 + kt * 8 + ql;\
        af[kt][0] = ap[0];                                                   \
        af[kt][1] = ap[8 * S2Q];                                             \
        af[kt][2] = ap[4];                                                   \
        af[kt][3] = ap[8 * S2Q + 4];                                         \
    }                                                                        \
} while (0)

#define ZERO_ACC(A) do {                                                     \
    _Pragma("unroll")                                                        \
    for (int nt = 0; nt < 8; ++nt)                                           \
        { A[nt][0] = 0.f; A[nt][1] = 0.f; A[nt][2] = 0.f; A[nt][3] = 0.f; }  \
} while (0)

// ---------------- main fused kernel: one CTA per (window, branch) ----------------
__global__ void __launch_bounds__(THREADS, 2)
swin_branch_kernel(const float* __restrict__ x,
                   const float* __restrict__ qb, const float* __restrict__ kb,
                   const float* __restrict__ vb, const float* __restrict__ pb,
                   const float* __restrict__ ls, float* __restrict__ out)
{
    extern __shared__ uint32_t smU[];
    uint32_t* qs2   = smU + OFF_Q;    // x / q / O as fp16 pairs (64 x 68)
    uint32_t* kbufU = smU + OFF_K;    // K d-pair transposed [d/2=64][key 64] (stride 72)
    uint32_t* vbufU = smU + OFF_V;    // V token-pair [tok/2=32][d 128] (stride 136)
    uint32_t* wstA  = smU + OFF_WA;
    uint32_t* wstB  = smU + OFF_WB;

    const int bid  = blockIdx.x;
    const int win  = bid >> 1;
    const int s    = bid & 1;               // branch (heads s*4..s*4+3)
    const int tid  = threadIdx.x;
    const int warp = tid >> 5;
    const int lane = tid & 31;
    const int r0   = (warp & 3) * 16;
    const int n0   = (warp >> 2) * 64;
    const int qr   = lane >> 2;
    const int ql   = lane & 3;
    const int ldrow = tid >> 5;             // staging row base 0..7
    const int ldcol = (tid & 31) * 4;       // staging col (uint32) 0..124

    const uint32_t wA_u = (uint32_t)__cvta_generic_to_shared(wstA);
    const uint32_t wB_u = (uint32_t)__cvta_generic_to_shared(wstB);

    uint32_t af[4][4];

    ISSUE(WSRC(0, 0), wA_u);               // prefetch Q weights half 0

    // load x branch slice [64][128] -> fp16 pairs in qs
    const float4* xg4 = (const float4*)(x + (size_t)win * (NTOK * CDIM));
    for (int t = tid; t < 64 * 32; t += THREADS) {
        int i = t >> 5, j = t & 31;         // j: float4 index within 128-col slice
        float4 v = xg4[i * 64 + s * 32 + j];
        uint2 st; st.x = pkh2(v.x, v.y); st.y = pkh2(v.z, v.w);
        *(uint2*)&qs2[i * S2Q + j * 2] = st;
    }
    __syncthreads();

    // =========== Phase 1: Q, K, V residual linears ===========
    float accQ[8][4];
    ZERO_ACC(accQ);
    {
        LOAD_AF(0);
        WAITSYNC(); ISSUE(WSRC(0, 1), wB_u);
        MMA_LOOP(wstA, accQ);
        LOAD_AF(1);
        WAITSYNC(); ISSUE(WSRC(1, 0), wA_u);
        MMA_LOOP(wstB, accQ);

        float accK[8][4];
        ZERO_ACC(accK);
        LOAD_AF(0);
        WAITSYNC(); ISSUE(WSRC(1, 1), wB_u);
        MMA_LOOP(wstA, accK);
        LOAD_AF(1);
        WAITSYNC(); ISSUE(WSRC(2, 0), wA_u);
        MMA_LOOP(wstB, accK);

        // k epilogue: k = x + acc + kb -> kbuf d-pair transposed [c/2][key]
        {
            const int rr = r0 + qr;
#pragma unroll
            for (int nt = 0; nt < 8; ++nt) {
                const int c = n0 + nt * 8 + 2 * ql;      // even
                float2 x0 = uph2(qs2[rr * S2Q + (c >> 1)]);
                float2 x1 = uph2(qs2[(rr + 8) * S2Q + (c >> 1)]);
                float2 kb2 = *(const float2*)&kb[s * 128 + c];
                kbufU[(c >> 1) * S2K + rr] =
                    pkh2(x0.x + accK[nt][0] + kb2.x, x0.y + accK[nt][1] + kb2.y);
                kbufU[(c >> 1) * S2K + rr + 8] =
                    pkh2(x1.x + accK[nt][2] + kb2.x, x1.y + accK[nt][3] + kb2.y);
            }
        }
    }
    {
        float accV[8][4];
        ZERO_ACC(accV);
        LOAD_AF(0);
        WAITSYNC(); ISSUE(WSRC(2, 1), wB_u);
        MMA_LOOP(wstA, accV);
        LOAD_AF(1);
        WAITSYNC(); ISSUE(WSRC(3, 0), wA_u);   // P weights half 0 (wstA free: all warps past MMA A)
        MMA_LOOP(wstB, accV);

        // v epilogue (token-pair pack via lane-xor-4 exchange), then q epilogue
        {
            const int rr = r0 + qr;
            const int m0 = rr >> 1;              // token-pair row (group 0)
            const uint32_t psel = (qr & 1) ? 0x3276u : 0x5410u;
            const int cofs = (qr & 1);
#pragma unroll
            for (int nt = 0; nt < 8; ++nt) {
                const int c = n0 + nt * 8 + 2 * ql;
                float2 x0 = uph2(qs2[rr * S2Q + (c >> 1)]);
                float2 x1 = uph2(qs2[(rr + 8) * S2Q + (c >> 1)]);
                float2 vb2 = *(const float2*)&vb[s * 128 + c];
                float2 qb2 = *(const float2*)&qb[s * 128 + c];

                uint32_t mine0 = pkh2(x0.x + accV[nt][0] + vb2.x, x0.y + accV[nt][1] + vb2.y);
                uint32_t mine1 = pkh2(x1.x + accV[nt][2] + vb2.x, x1.y + accV[nt][3] + vb2.y);
                uint32_t oth0 = __shfl_xor_sync(0xffffffffu, mine0, 4);
                uint32_t oth1 = __shfl_xor_sync(0xffffffffu, mine1, 4);
                vbufU[m0 * S2V + c + cofs]       = __byte_perm(mine0, oth0, psel);
                vbufU[(m0 + 4) * S2V + c + cofs] = __byte_perm(mine1, oth1, psel);

                qs2[rr * S2Q + (c >> 1)] =
                    pkh2(x0.x + accQ[nt][0] + qb2.x, x0.y + accQ[nt][1] + qb2.y);
                qs2[(rr + 8) * S2Q + (c >> 1)] =
                    pkh2(x1.x + accQ[nt][2] + qb2.x, x1.y + accQ[nt][3] + qb2.y);
            }
        }
    }
    __syncthreads();
    ISSUE(WSRC(3, 1), wB_u);   // P weights half 1 (wstB free: all warps past MMA B)

    // =========== Phase 2: l2-normalize q (qs) and k (kbuf); fold logit scale ===========
#pragma unroll
    for (int t4 = 0; t4 < 2; ++t4) {
        int t = tid + t4 * THREADS;          // 512 tasks
        int bufsel = t >> 8;
        int h = (t >> 6) & 3;
        int i = t & 63;
        if (bufsel == 0) {
            uint32_t* base = qs2 + i * S2Q + h * 16;
            uint4 r[4];
            float ssq = 0.f;
#pragma unroll
            for (int u = 0; u < 4; ++u) {
                r[u] = ((uint4*)base)[u];
                float2 f0 = uph2(r[u].x), f1 = uph2(r[u].y);
                float2 f2 = uph2(r[u].z), f3 = uph2(r[u].w);
                ssq += f0.x * f0.x + f0.y * f0.y + f1.x * f1.x + f1.y * f1.y
                     + f2.x * f2.x + f2.y * f2.y + f3.x * f3.x + f3.y * f3.y;
            }
            float inv = fminf(expf(ls[s * 4 + h]), 100.f) / fmaxf(sqrtf(ssq), 1e-12f);
#pragma unroll
            for (int u = 0; u < 4; ++u) {
                uint4 w;
                float2 f0 = uph2(r[u].x), f1 = uph2(r[u].y);
                float2 f2 = uph2(r[u].z), f3 = uph2(r[u].w);
                w.x = pkh2(f0.x * inv, f0.y * inv);
                w.y = pkh2(f1.x * inv, f1.y * inv);
                w.z = pkh2(f2.x * inv, f2.y * inv);
                w.w = pkh2(f3.x * inv, f3.y * inv);
                ((uint4*)base)[u] = w;
            }
        } else {
            uint32_t r[16];
            float ssq = 0.f;
#pragma unroll
            for (int kk = 0; kk < 16; ++kk) {
                r[kk] = kbufU[(h * 16 + kk) * S2K + i];
                float2 f = uph2(r[kk]);
                ssq += f.x * f.x + f.y * f.y;
            }
            float inv = 1.f / fmaxf(sqrtf(ssq), 1e-12f);
#pragma unroll
            for (int kk = 0; kk < 16; ++kk) {
                float2 f = uph2(r[kk]);
                kbufU[(h * 16 + kk) * S2K + i] = pkh2(f.x * inv, f.y * inv);
            }
        }
    }
    __syncthreads();

    // =========== Phase 3: attention (fp16 mma), two warps per head ===========
    {
        const int h = warp >> 1;
        const int mtb = (warp & 1) * 2;
        const float* Tw = d_Tcomb +
            (size_t)((((win & (NWIN - 1)) * NHEADS + s * 4 + h)) << 12);

#pragma unroll 1
        for (int mm = 0; mm < 2; ++mm) {
            const int i0r = (mtb + mm) * 16 + qr;

            uint32_t qa[2][4];
#pragma unroll
            for (int kt = 0; kt < 2; ++kt) {
                const uint32_t* ap = qs2 + i0r * S2Q + h * 16 + kt * 8 + ql;
                qa[kt][0] = ap[0];
                qa[kt][1] = ap[8 * S2Q];
                qa[kt][2] = ap[4];
                qa[kt][3] = ap[8 * S2Q + 4];
            }

            float S[8][4];
#pragma unroll
            for (int nt = 0; nt < 8; ++nt) { S[nt][0] = S[nt][1] = S[nt][2] = S[nt][3] = 0.f; }
#pragma unroll
            for (int kt = 0; kt < 2; ++kt) {
                const uint32_t* bp = kbufU + (h * 16 + kt * 8 + ql) * S2K + qr;
#pragma unroll
                for (int nt = 0; nt < 8; ++nt) {
                    mma_f16(S[nt][0], S[nt][1], S[nt][2], S[nt][3],
                            qa[kt][0], qa[kt][1], qa[kt][2], qa[kt][3],
                            bp[nt * 8], bp[4 * S2K + nt * 8]);
                }
            }

            float rmax0 = -1e30f, rmax1 = -1e30f;
#pragma unroll
            for (int nt = 0; nt < 8; ++nt) {
                float2 t0 = *(const float2*)&Tw[i0r * 64 + nt * 8 + 2 * ql];
                float2 t1 = *(const float2*)&Tw[(i0r + 8) * 64 + nt * 8 + 2 * ql];
                S[nt][0] += t0.x; S[nt][1] += t0.y;
                S[nt][2] += t1.x; S[nt][3] += t1.y;
                rmax0 = fmaxf(rmax0, fmaxf(S[nt][0], S[nt][1]));
                rmax1 = fmaxf(rmax1, fmaxf(S[nt][2], S[nt][3]));
            }
            rmax0 = fmaxf(rmax0, __shfl_xor_sync(0xffffffffu, rmax0, 1));
            rmax0 = fmaxf(rmax0, __shfl_xor_sync(0xffffffffu, rmax0, 2));
            rmax1 = fmaxf(rmax1, __shfl_xor_sync(0xffffffffu, rmax1, 1));
            rmax1 = fmaxf(rmax1, __shfl_xor_sync(0xffffffffu, rmax1, 2));

            float sum0 = 0.f, sum1 = 0.f;
#pragma unroll
            for (int nt = 0; nt < 8; ++nt) {
                S[nt][0] = __expf(S[nt][0] - rmax0); sum0 += S[nt][0];
                S[nt][1] = __expf(S[nt][1] - rmax0); sum0 += S[nt][1];
                S[nt][2] = __expf(S[nt][2] - rmax1); sum1 += S[nt][2];
                S[nt][3] = __expf(S[nt][3] - rmax1); sum1 += S[nt][3];
            }
            sum0 += __shfl_xor_sync(0xffffffffu, sum0, 1);
            sum0 += __shfl_xor_sync(0xffffffffu, sum0, 2);
            sum1 += __shfl_xor_sync(0xffffffffu, sum1, 1);
            sum1 += __shfl_xor_sync(0xffffffffu, sum1, 2);
            float inv0 = 1.f / sum0, inv1 = 1.f / sum1;

            // P -> A-fragments: fp16 C/A layouts coincide, no shuffles
            uint32_t pa[4][4];
#pragma unroll
            for (int kt = 0; kt < 4; ++kt) {
                pa[kt][0] = pkh2(S[2 * kt][0] * inv0, S[2 * kt][1] * inv0);
                pa[kt][1] = pkh2(S[2 * kt][2] * inv1, S[2 * kt][3] * inv1);
                pa[kt][2] = pkh2(S[2 * kt + 1][0] * inv0, S[2 * kt + 1][1] * inv0);
                pa[kt][3] = pkh2(S[2 * kt + 1][2] * inv1, S[2 * kt + 1][3] * inv1);
            }

            float O[4][4];
#pragma unroll
            for (int nd = 0; nd < 4; ++nd) { O[nd][0] = O[nd][1] = O[nd][2] = O[nd][3] = 0.f; }
#pragma unroll
            for (int kt = 0; kt < 4; ++kt) {
                const uint32_t* vp = vbufU + (kt * 8 + ql) * S2V + h * 32 + qr;
#pragma unroll
                for (int nd = 0; nd < 4; ++nd) {
                    mma_f16(O[nd][0], O[nd][1], O[nd][2], O[nd][3],
                            pa[kt][0], pa[kt][1], pa[kt][2], pa[kt][3],
                            vp[nd * 8], vp[4 * S2V + nd * 8]);
                }
            }

            // O (already normalized) -> fp16 pairs into qs
#pragma unroll
            for (int nd = 0; nd < 4; ++nd) {
                qs2[i0r * S2Q + h * 16 + nd * 4 + ql] = pkh2(O[nd][0], O[nd][1]);
                qs2[(i0r + 8) * S2Q + h * 16 + nd * 4 + ql] = pkh2(O[nd][2], O[nd][3]);
            }
        }
    }
    __syncthreads();

    // =========== Phase 4: output projection (P weights already staged) ===========
    float* og = out + (size_t)win * (NTOK * CDIM);
    {
        float accP[8][4];
        ZERO_ACC(accP);
        LOAD_AF(0);
        WAITSYNC();                  // both P halves complete; O visible from sync above
        MMA_LOOP(wstA, accP);
        LOAD_AF(1);
        MMA_LOOP(wstB, accP);

        const int rr = r0 + qr;
#pragma unroll
        for (int nt = 0; nt < 8; ++nt) {
            const int c = n0 + nt * 8 + 2 * ql;
            float2 pb2 = *(const float2*)&pb[s * 128 + c];
            *(float2*)&og[rr * CDIM + s * 128 + c] =
                make_float2(accP[nt][0] + pb2.x, accP[nt][1] + pb2.y);
            *(float2*)&og[(rr + 8) * CDIM + s * 128 + c] =
                make_float2(accP[nt][2] + pb2.x, accP[nt][3] + pb2.y);
        }
    }
}

extern "C" void kernel_launch(void* const* d_in, const int* in_sizes, int n_in,
                              void* d_out, int out_size) {
    const float* x    = (const float*)d_in[0];
    const float* mask = (const float*)d_in[1];
    const float* qw   = (const float*)d_in[2];
    const float* qb   = (const float*)d_in[3];
    const float* kw   = (const float*)d_in[4];
    const float* kb   = (const float*)d_in[5];
    const float* vw   = (const float*)d_in[6];
    const float* vb   = (const float*)d_in[7];
    const float* pw   = (const float*)d_in[8];
    const float* pb   = (const float*)d_in[9];
    const float* w1   = (const float*)d_in[10];
    const float* b1   = (const float*)d_in[11];
    const float* w2   = (const float*)d_in[12];
    const float* ls   = (const float*)d_in[13];
    const float* rpb  = (const float*)d_in[14];
    const int*   rpi  = (const int*)d_in[15];
    float* out = (float*)d_out;

    static bool inited = false;
    if (!inited) {
        cudaFuncSetAttribute(swin_branch_kernel,
                             cudaFuncAttributeMaxDynamicSharedMemorySize, SMEM_BYTES);
        inited = true;
    }

    whconv_kernel<<<256, 256>>>(qw, kw, vw, pw);
    cpb_mlp_kernel<<<225, 128>>>(rpb, w1, b1, w2);
    bias_combine_kernel<<<(NWIN * NHEADS * NTOK * NTOK + 255) / 256, 256>>>(rpi, mask);
    swin_branch_kernel<<<NBATCH * 2, THREADS, SMEM_BYTES>>>(x, qb, kb, vb, pb, ls, out);
}

// round 13
// speedup vs baseline: 3.0471x; 1.0399x over previous
#include <cuda_runtime.h>
#include <cuda_fp16.h>
#include <math.h>
#include <stdint.h>

#define NTOK 64
#define CDIM 256
#define NHEADS 8
#define HD   32
#define NWIN 64
#define NBATCH 2048
#define THREADS 256

// strides in uint32 (half2) units
#define S2Q 68            // qs: 4 mod 32 -> conflict-free qr-row access
#define S2K 72            // kbuf: 8 mod 32 -> conflict-free ql-row access
#define S2V 136           // vbuf: 8 mod 32
#define S2W 136           // weight stages: 8 mod 32

// smem layout (uint32 units)
#define OFF_Q  0                        // 64 x 68
#define OFF_K  (64 * S2Q)               // 64 x 72
#define OFF_V  (OFF_K + 64 * S2K)       // 32 x 136
#define OFF_WA (OFF_V + 32 * S2V)       // 32 x 136
#define OFF_WB (OFF_WA + 32 * S2W)      // 32 x 136
#define SMEM_U32 (OFF_WB + 32 * S2W)
#define SMEM_BYTES (SMEM_U32 * 4)       // 88064 B -> 2 CTAs/SM

__device__ float d_tbl2[225 * NHEADS];
__device__ float d_Tcomb[NWIN * NHEADS * NTOK * NTOK];   // 16*sigmoid(bias)+mask, 8MB
__device__ uint32_t d_wh[4 * 2 * 2 * 32 * 128];          // fp16 k-pair packed weights

// ---------------- helpers ----------------
__device__ __forceinline__ uint32_t pkh2(float a, float b) {
    __half2 h = __floats2half2_rn(a, b);
    return *reinterpret_cast<uint32_t*>(&h);
}
__device__ __forceinline__ float2 uph2(uint32_t u) {
    __half2 h = *reinterpret_cast<__half2*>(&u);
    return __half22float2(h);
}

// ---------------- prologue 0: weights -> fp16 k-pair pack ----------------
__global__ void whconv_kernel(const float* __restrict__ qw, const float* __restrict__ kw,
                              const float* __restrict__ vw, const float* __restrict__ pw) {
    int idx = blockIdx.x * blockDim.x + threadIdx.x;
    if (idx >= 4 * 2 * 2 * 32 * 128) return;
    int w  = idx >> 14;
    int s  = (idx >> 13) & 1;
    int hf = (idx >> 12) & 1;
    int kk = (idx >> 7) & 31;
    int n  = idx & 127;
    const float* src = (w == 0) ? qw : (w == 1) ? kw : (w == 2) ? vw : pw;
    int c = hf * 64 + 2 * kk;
    float v0 = src[s * 16384 + c * 128 + n];
    float v1 = src[s * 16384 + (c + 1) * 128 + n];
    d_wh[idx] = pkh2(v0, v1);
}

// ---------------- prologue 1: rpb_table -> MLP -> (225, 8) ----------------
__global__ void cpb_mlp_kernel(const float* __restrict__ rpb,
                               const float* __restrict__ w1,
                               const float* __restrict__ b1,
                               const float* __restrict__ w2) {
    __shared__ float acc[NHEADS];
    int p = blockIdx.x;
    int j = threadIdx.x;
    if (j < NHEADS) acc[j] = 0.f;
    __syncthreads();
    float t0 = rpb[p * 2 + 0];
    float t1 = rpb[p * 2 + 1];
    float hid = fmaxf(t0 * w1[j] + t1 * w1[128 + j] + b1[j], 0.f);
#pragma unroll
    for (int h = 0; h < NHEADS; ++h) {
        float pv = hid * w2[j * 8 + h];
#pragma unroll
        for (int o = 16; o; o >>= 1) pv += __shfl_xor_sync(0xffffffffu, pv, o);
        if ((j & 31) == 0) atomicAdd(&acc[h], pv);
    }
    __syncthreads();
    if (j < NHEADS) d_tbl2[p * 8 + j] = acc[j];
}

// ---------------- prologue 2: combined bias+mask table ----------------
__global__ void bias_combine_kernel(const int* __restrict__ rpi,
                                    const float* __restrict__ mask) {
    int idx = blockIdx.x * blockDim.x + threadIdx.x;
    if (idx >= NWIN * NHEADS * NTOK * NTOK) return;
    int ij = idx & 4095;
    int h  = (idx >> 12) & 7;
    int w  = idx >> 15;
    float bv = d_tbl2[rpi[ij] * 8 + h];
    d_Tcomb[idx] = 16.f / (1.f + expf(-bv)) + mask[w * 4096 + ij];
}

// ---------------- fp16 mma m16n8k16 ----------------
__device__ __forceinline__ void mma_f16(float& d0, float& d1, float& d2, float& d3,
                                        uint32_t a0, uint32_t a1, uint32_t a2, uint32_t a3,
                                        uint32_t b0, uint32_t b1) {
    asm volatile(
        "mma.sync.aligned.m16n8k16.row.col.f32.f16.f16.f32 "
        "{%0,%1,%2,%3},{%4,%5,%6,%7},{%8,%9},{%0,%1,%2,%3};"
        : "+f"(d0), "+f"(d1), "+f"(d2), "+f"(d3)
        : "r"(a0), "r"(a1), "r"(a2), "r"(a3), "r"(b0), "r"(b1));
}

// weight source: w 0..3 = q,k,v,p; half hf -> [32 kk][128 n] uint32 block
#define WSRC(w, hf) (d_wh + (((w) * 2 + s) * 2 + (hf)) * 4096)

// stage one [32 kk][128 n] uint32 weight half via 4 cp.async per thread
#define ISSUE(SRC, DSTU) do {                                                \
    const uint32_t* _s0 = (SRC) + ldrow * 128 + ldcol;                       \
    uint32_t _d0 = (DSTU) + (uint32_t)((ldrow * S2W + ldcol) * 4);           \
    _Pragma("unroll")                                                        \
    for (int k_ = 0; k_ < 4; ++k_)                                           \
        asm volatile("cp.async.cg.shared.global [%0], [%1], 16;\n"           \
            :: "r"(_d0 + (uint32_t)(k_ * 8 * S2W * 4)),                      \
               "l"(_s0 + k_ * 8 * 128) : "memory");                          \
    asm volatile("cp.async.commit_group;\n" ::: "memory");                   \
} while (0)

#define WAITSYNC() do {                                                      \
    asm volatile("cp.async.wait_group 0;\n" ::: "memory");                   \
    __syncthreads();                                                         \
} while (0)

// 32x32 warp-tile fp16 mma over one staged weight half, A from af[AH]
#define MMA_LOOP(BUFU, ACC, AH) do {                                         \
    const uint32_t* _bu = (BUFU);                                            \
    _Pragma("unroll")                                                        \
    for (int kt = 0; kt < 4; ++kt) {                                         \
        const uint32_t* bp = _bu + (kt * 8 + ql) * S2W + n0 + qr;            \
        _Pragma("unroll")                                                    \
        for (int nt = 0; nt < 4; ++nt) {                                     \
            uint32_t b0_ = bp[nt * 8], b1_ = bp[4 * S2W + nt * 8];           \
            mma_f16(ACC[0][nt][0], ACC[0][nt][1], ACC[0][nt][2], ACC[0][nt][3], \
                    af[AH][0][kt][0], af[AH][0][kt][1], af[AH][0][kt][2], af[AH][0][kt][3], \
                    b0_, b1_);                                               \
            mma_f16(ACC[1][nt][0], ACC[1][nt][1], ACC[1][nt][2], ACC[1][nt][3], \
                    af[AH][1][kt][0], af[AH][1][kt][1], af[AH][1][kt][2], af[AH][1][kt][3], \
                    b0_, b1_);                                               \
        }                                                                    \
    }                                                                        \
} while (0)

// load A fragments for half HF into af[HF] (2 row tiles x 4 k16 tiles)
#define LOAD_AF_H(HF) do {                                                   \
    _Pragma("unroll")                                                        \
    for (int mt = 0; mt < 2; ++mt)                                           \
    _Pragma("unroll")                                                        \
    for (int kt = 0; kt < 4; ++kt) {                                         \
        const uint32_t* ap = qs2 + (r0 + mt * 16 + qr) * S2Q + (HF) * 32 + kt * 8 + ql; \
        af[HF][mt][kt][0] = ap[0];                                           \
        af[HF][mt][kt][1] = ap[8 * S2Q];                                     \
        af[HF][mt][kt][2] = ap[4];                                           \
        af[HF][mt][kt][3] = ap[8 * S2Q + 4];                                 \
    }                                                                        \
} while (0)

#define ZERO_ACC(A) do {                                                     \
    _Pragma("unroll")                                                        \
    for (int mt = 0; mt < 2; ++mt)                                           \
    _Pragma("unroll")                                                        \
    for (int nt = 0; nt < 4; ++nt)                                           \
        { A[mt][nt][0] = 0.f; A[mt][nt][1] = 0.f; A[mt][nt][2] = 0.f; A[mt][nt][3] = 0.f; } \
} while (0)

// ---------------- main fused kernel: one CTA per (window, branch) ----------------
__global__ void __launch_bounds__(THREADS, 2)
swin_branch_kernel(const float* __restrict__ x,
                   const float* __restrict__ qb, const float* __restrict__ kb,
                   const float* __restrict__ vb, const float* __restrict__ pb,
                   const float* __restrict__ ls, float* __restrict__ out)
{
    extern __shared__ uint32_t smU[];
    uint32_t* qs2   = smU + OFF_Q;    // x / q / O as fp16 pairs (64 x 68)
    uint32_t* kbufU = smU + OFF_K;    // K d-pair transposed [d/2=64][key 64] (stride 72)
    uint32_t* vbufU = smU + OFF_V;    // V token-pair [tok/2=32][d 128] (stride 136)
    uint32_t* wstA  = smU + OFF_WA;
    uint32_t* wstB  = smU + OFF_WB;

    const int bid  = blockIdx.x;
    const int win  = bid >> 1;
    const int s    = bid & 1;               // branch (heads s*4..s*4+3)
    const int tid  = threadIdx.x;
    const int warp = tid >> 5;
    const int lane = tid & 31;
    const int r0   = (warp & 1) * 32;       // 32x32 warp tiles: 2 row x 4 col grid
    const int n0   = (warp >> 1) * 32;
    const int qr   = lane >> 2;
    const int ql   = lane & 3;
    const int ldrow = tid >> 5;             // staging row base 0..7
    const int ldcol = (tid & 31) * 4;       // staging col (uint32) 0..124

    const uint32_t wA_u = (uint32_t)__cvta_generic_to_shared(wstA);
    const uint32_t wB_u = (uint32_t)__cvta_generic_to_shared(wstB);

    uint32_t af[2][2][4][4];                // A frags, both halves, held across K/V/Q

    ISSUE(WSRC(1, 0), wA_u);               // prefetch K weights half 0

    // load x branch slice [64][128] -> fp16 pairs in qs
    const float4* xg4 = (const float4*)(x + (size_t)win * (NTOK * CDIM));
    for (int t = tid; t < 64 * 32; t += THREADS) {
        int i = t >> 5, j = t & 31;
        float4 v = xg4[i * 64 + s * 32 + j];
        uint2 st; st.x = pkh2(v.x, v.y); st.y = pkh2(v.z, v.w);
        *(uint2*)&qs2[i * S2Q + j * 2] = st;
    }
    __syncthreads();

    LOAD_AF_H(0);
    LOAD_AF_H(1);

    // =========== Phase 1: K, V, Q residual linears (single live acc set) ===========
    {
        // --- K GEMM ---
        float acc[2][4][4];
        ZERO_ACC(acc);
        WAITSYNC(); ISSUE(WSRC(1, 1), wB_u);
        MMA_LOOP(wstA, acc, 0);
        WAITSYNC(); ISSUE(WSRC(2, 0), wA_u);
        MMA_LOOP(wstB, acc, 1);

        // k epilogue: k = x + acc + kb -> kbuf d-pair transposed [c/2][key]
#pragma unroll
        for (int mt = 0; mt < 2; ++mt) {
            const int rr = r0 + mt * 16 + qr;
#pragma unroll
            for (int nt = 0; nt < 4; ++nt) {
                const int c = n0 + nt * 8 + 2 * ql;
                float2 x0 = uph2(qs2[rr * S2Q + (c >> 1)]);
                float2 x1 = uph2(qs2[(rr + 8) * S2Q + (c >> 1)]);
                float2 kb2 = *(const float2*)&kb[s * 128 + c];
                kbufU[(c >> 1) * S2K + rr] =
                    pkh2(x0.x + acc[mt][nt][0] + kb2.x, x0.y + acc[mt][nt][1] + kb2.y);
                kbufU[(c >> 1) * S2K + rr + 8] =
                    pkh2(x1.x + acc[mt][nt][2] + kb2.x, x1.y + acc[mt][nt][3] + kb2.y);
            }
        }
    }
    {
        // --- V GEMM ---
        float acc[2][4][4];
        ZERO_ACC(acc);
        WAITSYNC(); ISSUE(WSRC(2, 1), wB_u);
        MMA_LOOP(wstA, acc, 0);
        WAITSYNC(); ISSUE(WSRC(0, 0), wA_u);
        MMA_LOOP(wstB, acc, 1);

        // v epilogue: token-pair pack via lane-xor-4 exchange -> vbuf
#pragma unroll
        for (int mt = 0; mt < 2; ++mt) {
            const int rr = r0 + mt * 16 + qr;
            const int m0 = rr >> 1;
            const uint32_t psel = (qr & 1) ? 0x3276u : 0x5410u;
            const int cofs = (qr & 1);
#pragma unroll
            for (int nt = 0; nt < 4; ++nt) {
                const int c = n0 + nt * 8 + 2 * ql;
                float2 x0 = uph2(qs2[rr * S2Q + (c >> 1)]);
                float2 x1 = uph2(qs2[(rr + 8) * S2Q + (c >> 1)]);
                float2 vb2 = *(const float2*)&vb[s * 128 + c];
                uint32_t mine0 = pkh2(x0.x + acc[mt][nt][0] + vb2.x, x0.y + acc[mt][nt][1] + vb2.y);
                uint32_t mine1 = pkh2(x1.x + acc[mt][nt][2] + vb2.x, x1.y + acc[mt][nt][3] + vb2.y);
                uint32_t oth0 = __shfl_xor_sync(0xffffffffu, mine0, 4);
                uint32_t oth1 = __shfl_xor_sync(0xffffffffu, mine1, 4);
                vbufU[m0 * S2V + c + cofs]       = __byte_perm(mine0, oth0, psel);
                vbufU[(m0 + 4) * S2V + c + cofs] = __byte_perm(mine1, oth1, psel);
            }
        }
    }
    {
        // --- Q GEMM (epilogue overwrites x in qs) ---
        float acc[2][4][4];
        ZERO_ACC(acc);
        WAITSYNC(); ISSUE(WSRC(0, 1), wB_u);
        MMA_LOOP(wstA, acc, 0);
        WAITSYNC(); ISSUE(WSRC(3, 0), wA_u);   // P weights h0 (wstA reads done by the sync)
        MMA_LOOP(wstB, acc, 1);

        // q epilogue: own-position RMW on qs
#pragma unroll
        for (int mt = 0; mt < 2; ++mt) {
            const int rr = r0 + mt * 16 + qr;
#pragma unroll
            for (int nt = 0; nt < 4; ++nt) {
                const int c = n0 + nt * 8 + 2 * ql;
                float2 x0 = uph2(qs2[rr * S2Q + (c >> 1)]);
                float2 x1 = uph2(qs2[(rr + 8) * S2Q + (c >> 1)]);
                float2 qb2 = *(const float2*)&qb[s * 128 + c];
                qs2[rr * S2Q + (c >> 1)] =
                    pkh2(x0.x + acc[mt][nt][0] + qb2.x, x0.y + acc[mt][nt][1] + qb2.y);
                qs2[(rr + 8) * S2Q + (c >> 1)] =
                    pkh2(x1.x + acc[mt][nt][2] + qb2.x, x1.y + acc[mt][nt][3] + qb2.y);
            }
        }
    }
    __syncthreads();
    ISSUE(WSRC(3, 1), wB_u);   // P weights h1 (wstB reads complete: all warps past sync)

    // =========== Phase 2: l2-normalize q (qs) and k (kbuf); fold logit scale ===========
#pragma unroll
    for (int t4 = 0; t4 < 2; ++t4) {
        int t = tid + t4 * THREADS;          // 512 tasks
        int bufsel = t >> 8;
        int h = (t >> 6) & 3;
        int i = t & 63;
        if (bufsel == 0) {
            uint32_t* base = qs2 + i * S2Q + h * 16;
            uint4 r[4];
            float ssq = 0.f;
#pragma unroll
            for (int u = 0; u < 4; ++u) {
                r[u] = ((uint4*)base)[u];
                float2 f0 = uph2(r[u].x), f1 = uph2(r[u].y);
                float2 f2 = uph2(r[u].z), f3 = uph2(r[u].w);
                ssq += f0.x * f0.x + f0.y * f0.y + f1.x * f1.x + f1.y * f1.y
                     + f2.x * f2.x + f2.y * f2.y + f3.x * f3.x + f3.y * f3.y;
            }
            float inv = fminf(expf(ls[s * 4 + h]), 100.f) / fmaxf(sqrtf(ssq), 1e-12f);
#pragma unroll
            for (int u = 0; u < 4; ++u) {
                uint4 w;
                float2 f0 = uph2(r[u].x), f1 = uph2(r[u].y);
                float2 f2 = uph2(r[u].z), f3 = uph2(r[u].w);
                w.x = pkh2(f0.x * inv, f0.y * inv);
                w.y = pkh2(f1.x * inv, f1.y * inv);
                w.z = pkh2(f2.x * inv, f2.y * inv);
                w.w = pkh2(f3.x * inv, f3.y * inv);
                ((uint4*)base)[u] = w;
            }
        } else {
            uint32_t r[16];
            float ssq = 0.f;
#pragma unroll
            for (int kk = 0; kk < 16; ++kk) {
                r[kk] = kbufU[(h * 16 + kk) * S2K + i];
                float2 f = uph2(r[kk]);
                ssq += f.x * f.x + f.y * f.y;
            }
            float inv = 1.f / fmaxf(sqrtf(ssq), 1e-12f);
#pragma unroll
            for (int kk = 0; kk < 16; ++kk) {
                float2 f = uph2(r[kk]);
                kbufU[(h * 16 + kk) * S2K + i] = pkh2(f.x * inv, f.y * inv);
            }
        }
    }
    __syncthreads();

    // =========== Phase 3: attention (fp16 mma), two warps per head ===========
    {
        const int h = warp >> 1;
        const int mtb = (warp & 1) * 2;
        const float* Tw = d_Tcomb +
            (size_t)((((win & (NWIN - 1)) * NHEADS + s * 4 + h)) << 12);

#pragma unroll 1
        for (int mm = 0; mm < 2; ++mm) {
            const int i0r = (mtb + mm) * 16 + qr;

            uint32_t qa[2][4];
#pragma unroll
            for (int kt = 0; kt < 2; ++kt) {
                const uint32_t* ap = qs2 + i0r * S2Q + h * 16 + kt * 8 + ql;
                qa[kt][0] = ap[0];
                qa[kt][1] = ap[8 * S2Q];
                qa[kt][2] = ap[4];
                qa[kt][3] = ap[8 * S2Q + 4];
            }

            float S[8][4];
#pragma unroll
            for (int nt = 0; nt < 8; ++nt) { S[nt][0] = S[nt][1] = S[nt][2] = S[nt][3] = 0.f; }
#pragma unroll
            for (int kt = 0; kt < 2; ++kt) {
                const uint32_t* bp = kbufU + (h * 16 + kt * 8 + ql) * S2K + qr;
#pragma unroll
                for (int nt = 0; nt < 8; ++nt) {
                    mma_f16(S[nt][0], S[nt][1], S[nt][2], S[nt][3],
                            qa[kt][0], qa[kt][1], qa[kt][2], qa[kt][3],
                            bp[nt * 8], bp[4 * S2K + nt * 8]);
                }
            }

            float rmax0 = -1e30f, rmax1 = -1e30f;
#pragma unroll
            for (int nt = 0; nt < 8; ++nt) {
                float2 t0 = *(const float2*)&Tw[i0r * 64 + nt * 8 + 2 * ql];
                float2 t1 = *(const float2*)&Tw[(i0r + 8) * 64 + nt * 8 + 2 * ql];
                S[nt][0] += t0.x; S[nt][1] += t0.y;
                S[nt][2] += t1.x; S[nt][3] += t1.y;
                rmax0 = fmaxf(rmax0, fmaxf(S[nt][0], S[nt][1]));
                rmax1 = fmaxf(rmax1, fmaxf(S[nt][2], S[nt][3]));
            }
            rmax0 = fmaxf(rmax0, __shfl_xor_sync(0xffffffffu, rmax0, 1));
            rmax0 = fmaxf(rmax0, __shfl_xor_sync(0xffffffffu, rmax0, 2));
            rmax1 = fmaxf(rmax1, __shfl_xor_sync(0xffffffffu, rmax1, 1));
            rmax1 = fmaxf(rmax1, __shfl_xor_sync(0xffffffffu, rmax1, 2));

            float sum0 = 0.f, sum1 = 0.f;
#pragma unroll
            for (int nt = 0; nt < 8; ++nt) {
                S[nt][0] = __expf(S[nt][0] - rmax0); sum0 += S[nt][0];
                S[nt][1] = __expf(S[nt][1] - rmax0); sum0 += S[nt][1];
                S[nt][2] = __expf(S[nt][2] - rmax1); sum1 += S[nt][2];
                S[nt][3] = __expf(S[nt][3] - rmax1); sum1 += S[nt][3];
            }
            sum0 += __shfl_xor_sync(0xffffffffu, sum0, 1);
            sum0 += __shfl_xor_sync(0xffffffffu, sum0, 2);
            sum1 += __shfl_xor_sync(0xffffffffu, sum1, 1);
            sum1 += __shfl_xor_sync(0xffffffffu, sum1, 2);
            float inv0 = 1.f / sum0, inv1 = 1.f / sum1;

            // P -> A-fragments: fp16 C/A layouts coincide, no shuffles
            uint32_t pa[4][4];
#pragma unroll
            for (int kt = 0; kt < 4; ++kt) {
                pa[kt][0] = pkh2(S[2 * kt][0] * inv0, S[2 * kt][1] * inv0);
                pa[kt][1] = pkh2(S[2 * kt][2] * inv1, S[2 * kt][3] * inv1);
                pa[kt][2] = pkh2(S[2 * kt + 1][0] * inv0, S[2 * kt + 1][1] * inv0);
                pa[kt][3] = pkh2(S[2 * kt + 1][2] * inv1, S[2 * kt + 1][3] * inv1);
            }

            float O[4][4];
#pragma unroll
            for (int nd = 0; nd < 4; ++nd) { O[nd][0] = O[nd][1] = O[nd][2] = O[nd][3] = 0.f; }
#pragma unroll
            for (int kt = 0; kt < 4; ++kt) {
                const uint32_t* vp = vbufU + (kt * 8 + ql) * S2V + h * 32 + qr;
#pragma unroll
                for (int nd = 0; nd < 4; ++nd) {
                    mma_f16(O[nd][0], O[nd][1], O[nd][2], O[nd][3],
                            pa[kt][0], pa[kt][1], pa[kt][2], pa[kt][3],
                            vp[nd * 8], vp[4 * S2V + nd * 8]);
                }
            }

            // O (already normalized) -> fp16 pairs into qs
#pragma unroll
            for (int nd = 0; nd < 4; ++nd) {
                qs2[i0r * S2Q + h * 16 + nd * 4 + ql] = pkh2(O[nd][0], O[nd][1]);
                qs2[(i0r + 8) * S2Q + h * 16 + nd * 4 + ql] = pkh2(O[nd][2], O[nd][3]);
            }
        }
    }
    __syncthreads();

    // =========== Phase 4: output projection (P weights already staged) ===========
    float* og = out + (size_t)win * (NTOK * CDIM);
    {
        float acc[2][4][4];
        ZERO_ACC(acc);
        LOAD_AF_H(0);
        WAITSYNC();                  // both P halves complete
        MMA_LOOP(wstA, acc, 0);
        LOAD_AF_H(1);
        MMA_LOOP(wstB, acc, 1);

#pragma unroll
        for (int mt = 0; mt < 2; ++mt) {
            const int rr = r0 + mt * 16 + qr;
#pragma unroll
            for (int nt = 0; nt < 4; ++nt) {
                const int c = n0 + nt * 8 + 2 * ql;
                float2 pb2 = *(const float2*)&pb[s * 128 + c];
                *(float2*)&og[rr * CDIM + s * 128 + c] =
                    make_float2(acc[mt][nt][0] + pb2.x, acc[mt][nt][1] + pb2.y);
                *(float2*)&og[(rr + 8) * CDIM + s * 128 + c] =
                    make_float2(acc[mt][nt][2] + pb2.x, acc[mt][nt][3] + pb2.y);
            }
        }
    }
}

extern "C" void kernel_launch(void* const* d_in, const int* in_sizes, int n_in,
                              void* d_out, int out_size) {
    const float* x    = (const float*)d_in[0];
    const float* mask = (const float*)d_in[1];
    const float* qw   = (const float*)d_in[2];
    const float* qb   = (const float*)d_in[3];
    const float* kw   = (const float*)d_in[4];
    const float* kb   = (const float*)d_in[5];
    const float* vw   = (const float*)d_in[6];
    const float* vb   = (const float*)d_in[7];
    const float* pw   = (const float*)d_in[8];
    const float* pb   = (const float*)d_in[9];
    const float* w1   = (const float*)d_in[10];
    const float* b1   = (const float*)d_in[11];
    const float* w2   = (const float*)d_in[12];
    const float* ls   = (const float*)d_in[13];
    const float* rpb  = (const float*)d_in[14];
    const int*   rpi  = (const int*)d_in[15];
    float* out = (float*)d_out;

    static bool inited = false;
    if (!inited) {
        cudaFuncSetAttribute(swin_branch_kernel,
                             cudaFuncAttributeMaxDynamicSharedMemorySize, SMEM_BYTES);
        inited = true;
    }

    whconv_kernel<<<256, 256>>>(qw, kw, vw, pw);
    cpb_mlp_kernel<<<225, 128>>>(rpb, w1, b1, w2);
    bias_combine_kernel<<<(NWIN * NHEADS * NTOK * NTOK + 255) / 256, 256>>>(rpi, mask);
    swin_branch_kernel<<<NBATCH * 2, THREADS, SMEM_BYTES>>>(x, qb, kb, vb, pb, ls, out);
}